// round 2
// baseline (speedup 1.0000x reference)
#include <cuda_runtime.h>
#include <math.h>

#define NN 50000
#define EE 800000

// ---------------- device scratch (no allocation allowed) ----------------
__device__ float g_p [NN * 256];
__device__ float g_sA[NN * 256];
__device__ float g_sB[NN * 256];
__device__ float g_h [NN * 256];
__device__ float g_u [NN * 512];
__device__ float g_norm[EE];
__device__ float g_dinv[NN];
__device__ int   g_deg[NN];

__device__ __forceinline__ float gelu_f(float x) {
    return 0.5f * x * (1.0f + erff(x * 0.7071067811865476f));
}

// ---------------- degree / norm precompute ----------------
__global__ void deg_kernel(const int* __restrict__ dst, int* __restrict__ deg, int E) {
    int e = blockIdx.x * blockDim.x + threadIdx.x;
    if (e < E) atomicAdd(&deg[dst[e]], 1);
}

__global__ void dinv_kernel(const int* __restrict__ deg, float* __restrict__ dinv, int n) {
    int i = blockIdx.x * blockDim.x + threadIdx.x;
    if (i < n) dinv[i] = rsqrtf((float)deg[i] + 1.0f);
}

__global__ void norm_kernel(const int* __restrict__ src, const int* __restrict__ dst,
                            const float* __restrict__ dinv, float* __restrict__ nrm, int E) {
    int e = blockIdx.x * blockDim.x + threadIdx.x;
    if (e < E) nrm[e] = dinv[src[e]] * dinv[dst[e]];
}

// p[i,:] = dinv[i]^2 * h[i,:]   (self-loop term; also serves as the zero-init)
__global__ void init_p_kernel(const float* __restrict__ h, const float* __restrict__ dinv,
                              float* __restrict__ p, int total4, int shift) {
    int idx = blockIdx.x * blockDim.x + threadIdx.x;
    if (idx >= total4) return;
    int i = idx >> shift;
    float w = dinv[i]; w = w * w;
    float4 v = *(const float4*)(h + (size_t)idx * 4);
    v.x *= w; v.y *= w; v.z *= w; v.w *= w;
    *(float4*)(p + (size_t)idx * 4) = v;
}

// p[dst,:] += norm[e] * h[src,:]  via vectorized global reductions
__global__ void scatter_kernel(const float* __restrict__ h, const int* __restrict__ src,
                               const int* __restrict__ dst, const float* __restrict__ nrm,
                               float* __restrict__ p, int total4, int shift, int mask) {
    int idx = blockIdx.x * blockDim.x + threadIdx.x;
    if (idx >= total4) return;
    int e = idx >> shift;
    int c = idx & mask;
    int s  = src[e];
    int d_ = dst[e];
    float w = nrm[e];
    const float4 v = *(const float4*)(h + ((size_t)s << (shift + 2)) + (size_t)c * 4);
    float* addr = p + ((size_t)d_ << (shift + 2)) + (size_t)c * 4;
    asm volatile("red.global.add.v4.f32 [%0], {%1,%2,%3,%4};"
                 :: "l"(addr), "f"(v.x * w), "f"(v.y * w), "f"(v.z * w), "f"(v.w * w)
                 : "memory");
}

// ---------------- main fused SGEMM: BM=128, BN=128, BK=8, 256 thr, 8x8 ----
// out = act( A1@W1 [+ A2@W2] + b1 [+ b2] [+ addM] ), row-major. K % 8 == 0.
// Double-buffered shared memory, register-staged global prefetch.
template<int ACT, bool DUAL, bool ADDM>
__global__ __launch_bounds__(256)
void fused_gemm128(const float* __restrict__ A1, const float* __restrict__ W1, int K1,
                   const float* __restrict__ A2, const float* __restrict__ W2, int K2,
                   const float* __restrict__ b1, const float* __restrict__ b2,
                   const float* __restrict__ addM, float* __restrict__ out,
                   int M, int NC) {
    __shared__ float As[2][8][128];
    __shared__ float Bs[2][8][128];

    const int tid = threadIdx.x;
    const int rowBase = blockIdx.y * 128;
    const int colBase = blockIdx.x * 128;
    const int tmg = tid >> 4;            // 0..15, row group (x8)
    const int tng = tid & 15;            // 0..15, col group (x8)

    // loader coordinates
    const int lar = tid >> 1;            // A row in tile 0..127
    const int lac = (tid & 1) * 4;       // A k-offset {0,4}
    const int lbr = tid >> 5;            // B k-row 0..7
    const int lbc = (tid & 31) * 4;      // B col 0..124

    const bool aValid = (rowBase + lar) < M;

    float acc[8][8];
#pragma unroll
    for (int i = 0; i < 8; i++)
#pragma unroll
        for (int j = 0; j < 8; j++) acc[i][j] = 0.0f;

    const int nPhase = DUAL ? 2 : 1;
    for (int phase = 0; phase < nPhase; ++phase) {
        const float* A = (phase == 0) ? A1 : A2;
        const float* W = (phase == 0) ? W1 : W2;
        const int K    = (phase == 0) ? K1 : K2;

        const float* aPtr = A + (size_t)(rowBase + lar) * K + lac;
        const float* bPtr = W + (size_t)lbr * NC + colBase + lbc;

        // preload first tile into buffer 0
        {
            float4 av = aValid ? *(const float4*)aPtr : make_float4(0.f,0.f,0.f,0.f);
            float4 bv = *(const float4*)bPtr;
            As[0][lac + 0][lar] = av.x; As[0][lac + 1][lar] = av.y;
            As[0][lac + 2][lar] = av.z; As[0][lac + 3][lar] = av.w;
            *(float4*)&Bs[0][lbr][lbc] = bv;
        }
        __syncthreads();

        int buf = 0;
        for (int k0 = 0; k0 < K; k0 += 8) {
            const bool hasNext = (k0 + 8) < K;
            float4 av, bv;
            if (hasNext) {
                av = aValid ? *(const float4*)(aPtr + k0 + 8)
                            : make_float4(0.f,0.f,0.f,0.f);
                bv = *(const float4*)(bPtr + (size_t)(k0 + 8) * NC);
            }
#pragma unroll
            for (int kk = 0; kk < 8; kk++) {
                float4 a0 = *(const float4*)&As[buf][kk][tmg * 8];
                float4 a1 = *(const float4*)&As[buf][kk][tmg * 8 + 4];
                float4 b0 = *(const float4*)&Bs[buf][kk][tng * 8];
                float4 b1v = *(const float4*)&Bs[buf][kk][tng * 8 + 4];
                float a[8] = {a0.x, a0.y, a0.z, a0.w, a1.x, a1.y, a1.z, a1.w};
                float b[8] = {b0.x, b0.y, b0.z, b0.w, b1v.x, b1v.y, b1v.z, b1v.w};
#pragma unroll
                for (int i = 0; i < 8; i++)
#pragma unroll
                    for (int j = 0; j < 8; j++)
                        acc[i][j] = fmaf(a[i], b[j], acc[i][j]);
            }
            if (hasNext) {
                int nb = buf ^ 1;
                As[nb][lac + 0][lar] = av.x; As[nb][lac + 1][lar] = av.y;
                As[nb][lac + 2][lar] = av.z; As[nb][lac + 3][lar] = av.w;
                *(float4*)&Bs[nb][lbr][lbc] = bv;
            }
            __syncthreads();
            buf ^= 1;
        }
    }

    // epilogue
    float bias[8];
#pragma unroll
    for (int j = 0; j < 8; j++) {
        int col = colBase + tng * 8 + j;
        bias[j] = b1[col];
        if (DUAL) bias[j] += b2[col];
    }
#pragma unroll
    for (int i = 0; i < 8; i++) {
        int row = rowBase + tmg * 8 + i;
        if (row >= M) continue;
        float* orow = out + (size_t)row * NC + colBase + tng * 8;
        float vals[8];
#pragma unroll
        for (int j = 0; j < 8; j++) vals[j] = acc[i][j] + bias[j];
        if (ADDM) {
            const float* arow = addM + (size_t)row * NC + colBase + tng * 8;
            float4 m0 = *(const float4*)(arow);
            float4 m1 = *(const float4*)(arow + 4);
            vals[0] += m0.x; vals[1] += m0.y; vals[2] += m0.z; vals[3] += m0.w;
            vals[4] += m1.x; vals[5] += m1.y; vals[6] += m1.z; vals[7] += m1.w;
        }
        if (ACT == 1) {
#pragma unroll
            for (int j = 0; j < 8; j++) vals[j] = gelu_f(vals[j]);
        }
        *(float4*)(orow)     = make_float4(vals[0], vals[1], vals[2], vals[3]);
        *(float4*)(orow + 4) = make_float4(vals[4], vals[5], vals[6], vals[7]);
    }
}

// ---------------- narrow SGEMM for the final N=64 layer ----------------
// BM=128, BN=64, BK=16, 128 threads, 8x8 micro-tile.
template<int ACT>
__global__ __launch_bounds__(128)
void fused_gemm64(const float* __restrict__ A1, const float* __restrict__ W1, int K1,
                  const float* __restrict__ b1, float* __restrict__ out,
                  int M, int NC) {
    __shared__ float As[16][128];
    __shared__ float Bs[16][64];

    const int tid = threadIdx.x;
    const int rowBase = blockIdx.y * 128;
    const int colBase = blockIdx.x * 64;
    const int tmg = tid >> 3;
    const int tng = tid & 7;

    float acc[8][8];
#pragma unroll
    for (int i = 0; i < 8; i++)
#pragma unroll
        for (int j = 0; j < 8; j++) acc[i][j] = 0.0f;

    for (int k0 = 0; k0 < K1; k0 += 16) {
        __syncthreads();
#pragma unroll
        for (int i = 0; i < 4; i++) {
            int idx = tid + i * 128;
            int r  = idx >> 2;
            int c4 = (idx & 3) << 2;
            int row = rowBase + r;
            float4 v = make_float4(0.f, 0.f, 0.f, 0.f);
            if (row < M) v = *(const float4*)(A1 + (size_t)row * K1 + k0 + c4);
            As[c4 + 0][r] = v.x; As[c4 + 1][r] = v.y;
            As[c4 + 2][r] = v.z; As[c4 + 3][r] = v.w;
        }
#pragma unroll
        for (int i = 0; i < 2; i++) {
            int idx = tid + i * 128;
            int kr = idx >> 4;
            int c4 = (idx & 15) << 2;
            *(float4*)&Bs[kr][c4] =
                *(const float4*)(W1 + (size_t)(k0 + kr) * NC + colBase + c4);
        }
        __syncthreads();
#pragma unroll
        for (int kk = 0; kk < 16; kk++) {
            float4 a0 = *(const float4*)&As[kk][tmg * 8];
            float4 a1 = *(const float4*)&As[kk][tmg * 8 + 4];
            float4 b0 = *(const float4*)&Bs[kk][tng * 8];
            float4 b1v = *(const float4*)&Bs[kk][tng * 8 + 4];
            float a[8] = {a0.x, a0.y, a0.z, a0.w, a1.x, a1.y, a1.z, a1.w};
            float b[8] = {b0.x, b0.y, b0.z, b0.w, b1v.x, b1v.y, b1v.z, b1v.w};
#pragma unroll
            for (int i = 0; i < 8; i++)
#pragma unroll
                for (int j = 0; j < 8; j++)
                    acc[i][j] = fmaf(a[i], b[j], acc[i][j]);
        }
    }

    float bias[8];
#pragma unroll
    for (int j = 0; j < 8; j++) bias[j] = b1[colBase + tng * 8 + j];
#pragma unroll
    for (int i = 0; i < 8; i++) {
        int row = rowBase + tmg * 8 + i;
        if (row >= M) continue;
        float* orow = out + (size_t)row * NC + colBase + tng * 8;
        float vals[8];
#pragma unroll
        for (int j = 0; j < 8; j++) vals[j] = acc[i][j] + bias[j];
        if (ACT == 1) {
#pragma unroll
            for (int j = 0; j < 8; j++) vals[j] = gelu_f(vals[j]);
        }
        *(float4*)(orow)     = make_float4(vals[0], vals[1], vals[2], vals[3]);
        *(float4*)(orow + 4) = make_float4(vals[4], vals[5], vals[6], vals[7]);
    }
}

// ------- LayerNorm(d=256) + GELU, warp per row; optionally also emit ------
// ------- p = dinv^2 * gelu_out (self-loop init for the next layer)   ------
template<bool EMITP>
__global__ void ln_gelu_kernel(const float* __restrict__ in, const float* __restrict__ g,
                               const float* __restrict__ be, float* __restrict__ out,
                               const float* __restrict__ dinv, float* __restrict__ p,
                               int M) {
    int warp = blockIdx.x * 8 + (threadIdx.x >> 5);
    int lane = threadIdx.x & 31;
    if (warp >= M) return;
    const float* row = in + (size_t)warp * 256;
    float4 a = *(const float4*)(row + lane * 4);
    float4 b = *(const float4*)(row + 128 + lane * 4);
    float s = a.x + a.y + a.z + a.w + b.x + b.y + b.z + b.w;
#pragma unroll
    for (int o = 16; o; o >>= 1) s += __shfl_xor_sync(0xffffffffu, s, o);
    float mean = s * (1.0f / 256.0f);
    float d, v = 0.f;
    d = a.x - mean; v += d * d;  d = a.y - mean; v += d * d;
    d = a.z - mean; v += d * d;  d = a.w - mean; v += d * d;
    d = b.x - mean; v += d * d;  d = b.y - mean; v += d * d;
    d = b.z - mean; v += d * d;  d = b.w - mean; v += d * d;
#pragma unroll
    for (int o = 16; o; o >>= 1) v += __shfl_xor_sync(0xffffffffu, v, o);
    float rstd = rsqrtf(v * (1.0f / 256.0f) + 1e-5f);

    int c0 = lane * 4, c1 = 128 + lane * 4;
    float4 g0 = *(const float4*)(g + c0),  g1 = *(const float4*)(g + c1);
    float4 e0 = *(const float4*)(be + c0), e1 = *(const float4*)(be + c1);
    float4 o0, o1;
    o0.x = gelu_f((a.x - mean) * rstd * g0.x + e0.x);
    o0.y = gelu_f((a.y - mean) * rstd * g0.y + e0.y);
    o0.z = gelu_f((a.z - mean) * rstd * g0.z + e0.z);
    o0.w = gelu_f((a.w - mean) * rstd * g0.w + e0.w);
    o1.x = gelu_f((b.x - mean) * rstd * g1.x + e1.x);
    o1.y = gelu_f((b.y - mean) * rstd * g1.y + e1.y);
    o1.z = gelu_f((b.z - mean) * rstd * g1.z + e1.z);
    o1.w = gelu_f((b.w - mean) * rstd * g1.w + e1.w);
    float* orow = out + (size_t)warp * 256;
    *(float4*)(orow + lane * 4)       = o0;
    *(float4*)(orow + 128 + lane * 4) = o1;
    if (EMITP) {
        float w = dinv[warp]; w = w * w;
        float4 p0 = make_float4(o0.x * w, o0.y * w, o0.z * w, o0.w * w);
        float4 p1 = make_float4(o1.x * w, o1.y * w, o1.z * w, o1.w * w);
        float* prow = p + (size_t)warp * 256;
        *(float4*)(prow + lane * 4)       = p0;
        *(float4*)(prow + 128 + lane * 4) = p1;
    }
}

// ---------------- log_softmax over 64 cols, warp per row, in-place ----------------
__global__ void lsm_kernel(float* __restrict__ io, int M) {
    int warp = blockIdx.x * 8 + (threadIdx.x >> 5);
    int lane = threadIdx.x & 31;
    if (warp >= M) return;
    float* row = io + (size_t)warp * 64;
    float2 v = *(float2*)(row + lane * 2);
    float m = fmaxf(v.x, v.y);
#pragma unroll
    for (int o = 16; o; o >>= 1) m = fmaxf(m, __shfl_xor_sync(0xffffffffu, m, o));
    float s = expf(v.x - m) + expf(v.y - m);
#pragma unroll
    for (int o = 16; o; o >>= 1) s += __shfl_xor_sync(0xffffffffu, s, o);
    float l = m + logf(s);
    v.x -= l; v.y -= l;
    *(float2*)(row + lane * 2) = v;
}

// ---------------- host orchestration ----------------
extern "C" void kernel_launch(void* const* d_in, const int* in_sizes, int n_in,
                              void* d_out, int out_size) {
    const float* x   = (const float*)d_in[0];
    const int*   ei  = (const int*)d_in[1];
    const int*   src = ei;
    const int*   dst = ei + EE;
    const float* Wc[3] = {(const float*)d_in[2],  (const float*)d_in[8],  (const float*)d_in[14]};
    const float* bc[3] = {(const float*)d_in[3],  (const float*)d_in[9],  (const float*)d_in[15]};
    const float* Wp[3] = {(const float*)d_in[4],  (const float*)d_in[10], (const float*)d_in[16]};
    const float* bp[3] = {(const float*)d_in[5],  (const float*)d_in[11], (const float*)d_in[17]};
    const float* gn[3] = {(const float*)d_in[6],  (const float*)d_in[12], (const float*)d_in[18]};
    const float* be[3] = {(const float*)d_in[7],  (const float*)d_in[13], (const float*)d_in[19]};
    const float* W_in = (const float*)d_in[20];
    const float* b_in = (const float*)d_in[21];
    const float* Wf1  = (const float*)d_in[22];
    const float* bf1  = (const float*)d_in[23];
    const float* Wf2  = (const float*)d_in[24];
    const float* bf2  = (const float*)d_in[25];
    float* outp = (float*)d_out;

    float *p, *sA, *sB, *h, *u, *nrm, *dv;
    int* dg;
    cudaGetSymbolAddress((void**)&p,  g_p);
    cudaGetSymbolAddress((void**)&sA, g_sA);
    cudaGetSymbolAddress((void**)&sB, g_sB);
    cudaGetSymbolAddress((void**)&h,  g_h);
    cudaGetSymbolAddress((void**)&u,  g_u);
    cudaGetSymbolAddress((void**)&nrm, g_norm);
    cudaGetSymbolAddress((void**)&dv, g_dinv);
    cudaGetSymbolAddress((void**)&dg, g_deg);

    cudaMemsetAsync(dg, 0, NN * sizeof(int));
    deg_kernel<<<(EE + 255) / 256, 256>>>(dst, dg, EE);
    dinv_kernel<<<(NN + 255) / 256, 256>>>(dg, dv, NN);
    norm_kernel<<<(EE + 255) / 256, 256>>>(src, dst, dv, nrm, EE);

    const dim3 gridN256(256 / 128, (NN + 127) / 128);
    const dim3 gridN512(512 / 128, (NN + 127) / 128);
    const dim3 gridN64 (64 / 64,  (NN + 127) / 128);

    const float* hin  = x;   int din   = 128;
    const float* skip = x;   int dskip = 128;
    float* snew_arr[3] = {sA, sB, sA};

    for (int l = 0; l < 3; l++) {
        int shift = (din == 128) ? 5 : 6;
        int dq = din >> 2;
        int eTot = EE * dq;
        if (l == 0) {
            int nTot = NN * dq;
            init_p_kernel<<<(nTot + 255) / 256, 256>>>(hin, dv, p, nTot, shift);
        }
        // (for l >= 1 the previous ln_gelu already wrote p = dinv^2 * h)
        scatter_kernel<<<(eTot + 255) / 256, 256>>>(hin, src, dst, nrm, p, eTot, shift, dq - 1);
        float* snew = snew_arr[l];
        fused_gemm128<0, true, false><<<gridN256, 256>>>(
            p, Wc[l], din, skip, Wp[l], dskip,
            bc[l], bp[l], nullptr, snew, NN, 256);
        if (l < 2) {
            ln_gelu_kernel<true><<<(NN + 7) / 8, 256>>>(snew, gn[l], be[l], h, dv, p, NN);
        } else {
            ln_gelu_kernel<false><<<(NN + 7) / 8, 256>>>(snew, gn[l], be[l], h, nullptr, nullptr, NN);
        }
        hin = h; din = 256;
        skip = snew; dskip = 256;
    }

    // t = x @ W_in + b_in + h   (sB free after layer 2 consumed it as skip)
    fused_gemm128<0, false, true><<<gridN256, 256>>>(
        x, W_in, 128, nullptr, nullptr, 0, b_in, nullptr, h, sB, NN, 256);
    // u = gelu(t @ Wf1 + bf1)
    fused_gemm128<1, false, false><<<gridN512, 256>>>(
        sB, Wf1, 256, nullptr, nullptr, 0, bf1, nullptr, nullptr, u, NN, 512);
    // logits = u @ Wf2 + bf2  -> d_out
    fused_gemm64<0><<<gridN64, 128>>>(u, Wf2, 512, bf2, outp, NN, 64);
    // in-place log_softmax
    lsm_kernel<<<(NN + 7) / 8, 256>>>(outp, NN);
}

// round 4
// speedup vs baseline: 1.9023x; 1.9023x over previous
#include <cuda_runtime.h>
#include <math.h>
#include <stdint.h>

#define NN 50000
#define EE 800000

// ---------------- device scratch (no allocation allowed) ----------------
__device__ float g_p [NN * 256];
__device__ float g_sA[NN * 256];
__device__ float g_sB[NN * 256];
__device__ float g_h [NN * 256];
__device__ float g_u [NN * 512];
__device__ float g_norm[EE];
__device__ float g_dinv[NN];
__device__ int   g_deg[NN];

__device__ __forceinline__ float gelu_f(float x) {
    return 0.5f * x * (1.0f + erff(x * 0.7071067811865476f));
}

__device__ __forceinline__ uint32_t to_tf32(float x) {
    uint32_t r;
    asm("cvt.rna.tf32.f32 %0, %1;\n" : "=r"(r) : "f"(x));
    return r;
}

// ---------------- degree / norm precompute ----------------
__global__ void deg_kernel(const int* __restrict__ dst, int* __restrict__ deg, int E) {
    int e = blockIdx.x * blockDim.x + threadIdx.x;
    if (e < E) atomicAdd(&deg[dst[e]], 1);
}

__global__ void dinv_kernel(const int* __restrict__ deg, float* __restrict__ dinv, int n) {
    int i = blockIdx.x * blockDim.x + threadIdx.x;
    if (i < n) dinv[i] = rsqrtf((float)deg[i] + 1.0f);
}

__global__ void norm_kernel(const int* __restrict__ src, const int* __restrict__ dst,
                            const float* __restrict__ dinv, float* __restrict__ nrm, int E) {
    int e = blockIdx.x * blockDim.x + threadIdx.x;
    if (e < E) nrm[e] = dinv[src[e]] * dinv[dst[e]];
}

// p[i,:] = dinv[i]^2 * h[i,:]   (self-loop term; also serves as the zero-init)
__global__ void init_p_kernel(const float* __restrict__ h, const float* __restrict__ dinv,
                              float* __restrict__ p, int total4, int shift) {
    int idx = blockIdx.x * blockDim.x + threadIdx.x;
    if (idx >= total4) return;
    int i = idx >> shift;
    float w = dinv[i]; w = w * w;
    float4 v = *(const float4*)(h + (size_t)idx * 4);
    v.x *= w; v.y *= w; v.z *= w; v.w *= w;
    *(float4*)(p + (size_t)idx * 4) = v;
}

// p[dst,:] += norm[e] * h[src,:]  via vectorized global reductions
__global__ void scatter_kernel(const float* __restrict__ h, const int* __restrict__ src,
                               const int* __restrict__ dst, const float* __restrict__ nrm,
                               float* __restrict__ p, int total4, int shift, int mask) {
    int idx = blockIdx.x * blockDim.x + threadIdx.x;
    if (idx >= total4) return;
    int e = idx >> shift;
    int c = idx & mask;
    int s  = src[e];
    int d_ = dst[e];
    float w = nrm[e];
    const float4 v = *(const float4*)(h + ((size_t)s << (shift + 2)) + (size_t)c * 4);
    float* addr = p + ((size_t)d_ << (shift + 2)) + (size_t)c * 4;
    asm volatile("red.global.add.v4.f32 [%0], {%1,%2,%3,%4};"
                 :: "l"(addr), "f"(v.x * w), "f"(v.y * w), "f"(v.z * w), "f"(v.w * w)
                 : "memory");
}

// ---------------- tf32 tensor-core GEMM ----------------
// out = act( A1@W1 [+ A2@W2] + b1 [+ b2] [+ addM] ), row-major. K % 32 == 0.
// BM=128, BN in {128,64}, BK=32, 256 threads (8 warps, 4x2),
// warp tile 32 x (BN/2). cp.async double-buffered dynamic smem.
template<int BN, int ACT, bool DUAL, bool ADDM>
__global__ __launch_bounds__(256)
void tf32_gemm(const float* __restrict__ A1, const float* __restrict__ W1, int K1,
               const float* __restrict__ A2, const float* __restrict__ W2, int K2,
               const float* __restrict__ b1, const float* __restrict__ b2,
               const float* __restrict__ addM, float* __restrict__ out,
               int M, int NC) {
    constexpr int BM = 128, BK = 32;
    constexpr int ASTR = 36;          // A smem row stride (floats): banks (4m+k) bijective
    constexpr int BSTR = BN + 8;      // B smem row stride: 136/72, ≡8 mod 32 → (8k+n) bijective
    constexpr int AFL  = BM * ASTR;   // 4608 floats
    constexpr int BFL  = BK * BSTR;
    constexpr int BUFF = AFL + BFL;   // floats per pipeline stage
    constexpr int NT   = BN / 16;     // n-tiles (16x8 mma, 8 cols each) per warp

    extern __shared__ float smem[];

    const int tid  = threadIdx.x;
    const int lane = tid & 31;
    const int warp = tid >> 5;
    const int wm   = warp & 3;        // 0..3  -> 32-row slab
    const int wn   = warp >> 2;       // 0..1  -> BN/2-col slab
    const int gid  = lane >> 2;       // 0..7
    const int tig  = lane & 3;        // 0..3
    const int rowBase = blockIdx.y * BM;
    const int colBase = blockIdx.x * BN;

    const uint32_t sbase = (uint32_t)__cvta_generic_to_shared(smem);

    float acc[2][NT][4];
#pragma unroll
    for (int mt = 0; mt < 2; mt++)
#pragma unroll
        for (int nt = 0; nt < NT; nt++)
#pragma unroll
            for (int i = 0; i < 4; i++) acc[mt][nt][i] = 0.0f;

    const int nPhase = DUAL ? 2 : 1;
    for (int phase = 0; phase < nPhase; ++phase) {
        const float* A = (phase == 0) ? A1 : A2;
        const float* W = (phase == 0) ? W1 : W2;
        const int K    = (phase == 0) ? K1 : K2;
        const int nTiles = K / BK;

        // --- async tile copy: tile t -> buffer b ---
        auto cpTile = [&](int t, int b) {
            const int k0 = t * BK;
            const uint32_t aoff = sbase + (uint32_t)(b * BUFF) * 4u;
            const uint32_t boff = aoff + (uint32_t)AFL * 4u;
#pragma unroll
            for (int i = 0; i < 4; i++) {           // A: 128x32 = 1024 float4
                int idx = tid + i * 256;
                int r   = idx >> 3;
                int c4  = (idx & 7) << 2;
                int grow = rowBase + r;
                int sz = (grow < M) ? 16 : 0;
                const float* g = A + (size_t)((grow < M) ? grow : 0) * K + k0 + c4;
                uint32_t sa = aoff + (uint32_t)(r * ASTR + c4) * 4u;
                asm volatile("cp.async.ca.shared.global [%0], [%1], 16, %2;\n"
                             :: "r"(sa), "l"(g), "r"(sz));
            }
            constexpr int BI = (BN == 128) ? 4 : 2; // B: 32xBN float4s
#pragma unroll
            for (int i = 0; i < BI; i++) {
                int idx = tid + i * 256;
                int r   = idx >> ((BN == 128) ? 5 : 4);
                int c4  = (idx & ((BN / 4) - 1)) << 2;
                const float* g = W + (size_t)(k0 + r) * NC + colBase + c4;
                uint32_t sa = boff + (uint32_t)(r * BSTR + c4) * 4u;
                asm volatile("cp.async.ca.shared.global [%0], [%1], 16, %2;\n"
                             :: "r"(sa), "l"(g), "r"(16));
            }
            asm volatile("cp.async.commit_group;\n" ::);
        };

        int buf = 0;
        cpTile(0, 0);
        for (int t = 0; t < nTiles; t++) {
            const bool hasNext = (t + 1) < nTiles;
            if (hasNext) {
                cpTile(t + 1, buf ^ 1);
                asm volatile("cp.async.wait_group 1;\n" ::);
            } else {
                asm volatile("cp.async.wait_group 0;\n" ::);
            }
            __syncthreads();

            const float* As = smem + buf * BUFF;
            const float* Bs = As + AFL;
#pragma unroll
            for (int ks = 0; ks < 4; ks++) {
                const int k = ks * 8;
                uint32_t a[2][4];
                uint32_t b[NT][2];
#pragma unroll
                for (int mt = 0; mt < 2; mt++) {
                    int m = wm * 32 + mt * 16 + gid;
                    a[mt][0] = to_tf32(As[m * ASTR + k + tig]);
                    a[mt][1] = to_tf32(As[(m + 8) * ASTR + k + tig]);
                    a[mt][2] = to_tf32(As[m * ASTR + k + tig + 4]);
                    a[mt][3] = to_tf32(As[(m + 8) * ASTR + k + tig + 4]);
                }
#pragma unroll
                for (int nt = 0; nt < NT; nt++) {
                    int n = wn * (BN / 2) + nt * 8 + gid;
                    b[nt][0] = to_tf32(Bs[(k + tig) * BSTR + n]);
                    b[nt][1] = to_tf32(Bs[(k + tig + 4) * BSTR + n]);
                }
#pragma unroll
                for (int mt = 0; mt < 2; mt++)
#pragma unroll
                    for (int nt = 0; nt < NT; nt++) {
                        asm volatile(
                            "mma.sync.aligned.m16n8k8.row.col.f32.tf32.tf32.f32 "
                            "{%0,%1,%2,%3}, {%4,%5,%6,%7}, {%8,%9}, {%0,%1,%2,%3};\n"
                            : "+f"(acc[mt][nt][0]), "+f"(acc[mt][nt][1]),
                              "+f"(acc[mt][nt][2]), "+f"(acc[mt][nt][3])
                            : "r"(a[mt][0]), "r"(a[mt][1]), "r"(a[mt][2]), "r"(a[mt][3]),
                              "r"(b[nt][0]), "r"(b[nt][1]));
                    }
            }
            __syncthreads();   // protect buf before it is refilled next iteration
            buf ^= 1;
        }
    }

    // ---------------- epilogue ----------------
#pragma unroll
    for (int mt = 0; mt < 2; mt++) {
        const int r0 = rowBase + wm * 32 + mt * 16 + gid;
        const int r1 = r0 + 8;
#pragma unroll
        for (int nt = 0; nt < NT; nt++) {
            const int cn = colBase + wn * (BN / 2) + nt * 8 + tig * 2;
            float bias0 = b1[cn], bias1 = b1[cn + 1];
            if (DUAL) { bias0 += b2[cn]; bias1 += b2[cn + 1]; }
            float v0 = acc[mt][nt][0] + bias0;
            float v1 = acc[mt][nt][1] + bias1;
            float v2 = acc[mt][nt][2] + bias0;
            float v3 = acc[mt][nt][3] + bias1;
            if (r0 < M) {
                if (ADDM) {
                    float2 m0 = *(const float2*)(addM + (size_t)r0 * NC + cn);
                    v0 += m0.x; v1 += m0.y;
                }
                if (ACT == 1) { v0 = gelu_f(v0); v1 = gelu_f(v1); }
                *(float2*)(out + (size_t)r0 * NC + cn) = make_float2(v0, v1);
            }
            if (r1 < M) {
                if (ADDM) {
                    float2 m1 = *(const float2*)(addM + (size_t)r1 * NC + cn);
                    v2 += m1.x; v3 += m1.y;
                }
                if (ACT == 1) { v2 = gelu_f(v2); v3 = gelu_f(v3); }
                *(float2*)(out + (size_t)r1 * NC + cn) = make_float2(v2, v3);
            }
        }
    }
}

// ------- LayerNorm(d=256) + GELU, warp per row; optionally also emit ------
// ------- p = dinv^2 * gelu_out (self-loop init for the next layer)   ------
template<bool EMITP>
__global__ void ln_gelu_kernel(const float* __restrict__ in, const float* __restrict__ g,
                               const float* __restrict__ be, float* __restrict__ out,
                               const float* __restrict__ dinv, float* __restrict__ p,
                               int M) {
    int warp = blockIdx.x * 8 + (threadIdx.x >> 5);
    int lane = threadIdx.x & 31;
    if (warp >= M) return;
    const float* row = in + (size_t)warp * 256;
    float4 a = *(const float4*)(row + lane * 4);
    float4 b = *(const float4*)(row + 128 + lane * 4);
    float s = a.x + a.y + a.z + a.w + b.x + b.y + b.z + b.w;
#pragma unroll
    for (int o = 16; o; o >>= 1) s += __shfl_xor_sync(0xffffffffu, s, o);
    float mean = s * (1.0f / 256.0f);
    float d, v = 0.f;
    d = a.x - mean; v += d * d;  d = a.y - mean; v += d * d;
    d = a.z - mean; v += d * d;  d = a.w - mean; v += d * d;
    d = b.x - mean; v += d * d;  d = b.y - mean; v += d * d;
    d = b.z - mean; v += d * d;  d = b.w - mean; v += d * d;
#pragma unroll
    for (int o = 16; o; o >>= 1) v += __shfl_xor_sync(0xffffffffu, v, o);
    float rstd = rsqrtf(v * (1.0f / 256.0f) + 1e-5f);

    int c0 = lane * 4, c1 = 128 + lane * 4;
    float4 g0 = *(const float4*)(g + c0),  g1 = *(const float4*)(g + c1);
    float4 e0 = *(const float4*)(be + c0), e1 = *(const float4*)(be + c1);
    float4 o0, o1;
    o0.x = gelu_f((a.x - mean) * rstd * g0.x + e0.x);
    o0.y = gelu_f((a.y - mean) * rstd * g0.y + e0.y);
    o0.z = gelu_f((a.z - mean) * rstd * g0.z + e0.z);
    o0.w = gelu_f((a.w - mean) * rstd * g0.w + e0.w);
    o1.x = gelu_f((b.x - mean) * rstd * g1.x + e1.x);
    o1.y = gelu_f((b.y - mean) * rstd * g1.y + e1.y);
    o1.z = gelu_f((b.z - mean) * rstd * g1.z + e1.z);
    o1.w = gelu_f((b.w - mean) * rstd * g1.w + e1.w);
    float* orow = out + (size_t)warp * 256;
    *(float4*)(orow + lane * 4)       = o0;
    *(float4*)(orow + 128 + lane * 4) = o1;
    if (EMITP) {
        float w = dinv[warp]; w = w * w;
        float4 p0 = make_float4(o0.x * w, o0.y * w, o0.z * w, o0.w * w);
        float4 p1 = make_float4(o1.x * w, o1.y * w, o1.z * w, o1.w * w);
        float* prow = p + (size_t)warp * 256;
        *(float4*)(prow + lane * 4)       = p0;
        *(float4*)(prow + 128 + lane * 4) = p1;
    }
}

// ---------------- log_softmax over 64 cols, warp per row, in-place ----------------
__global__ void lsm_kernel(float* __restrict__ io, int M) {
    int warp = blockIdx.x * 8 + (threadIdx.x >> 5);
    int lane = threadIdx.x & 31;
    if (warp >= M) return;
    float* row = io + (size_t)warp * 64;
    float2 v = *(float2*)(row + lane * 2);
    float m = fmaxf(v.x, v.y);
#pragma unroll
    for (int o = 16; o; o >>= 1) m = fmaxf(m, __shfl_xor_sync(0xffffffffu, m, o));
    float s = expf(v.x - m) + expf(v.y - m);
#pragma unroll
    for (int o = 16; o; o >>= 1) s += __shfl_xor_sync(0xffffffffu, s, o);
    float l = m + logf(s);
    v.x -= l; v.y -= l;
    *(float2*)(row + lane * 2) = v;
}

// ---------------- host orchestration ----------------
extern "C" void kernel_launch(void* const* d_in, const int* in_sizes, int n_in,
                              void* d_out, int out_size) {
    const float* x   = (const float*)d_in[0];
    const int*   ei  = (const int*)d_in[1];
    const int*   src = ei;
    const int*   dst = ei + EE;
    const float* Wc[3] = {(const float*)d_in[2],  (const float*)d_in[8],  (const float*)d_in[14]};
    const float* bc[3] = {(const float*)d_in[3],  (const float*)d_in[9],  (const float*)d_in[15]};
    const float* Wp[3] = {(const float*)d_in[4],  (const float*)d_in[10], (const float*)d_in[16]};
    const float* bp[3] = {(const float*)d_in[5],  (const float*)d_in[11], (const float*)d_in[17]};
    const float* gn[3] = {(const float*)d_in[6],  (const float*)d_in[12], (const float*)d_in[18]};
    const float* be[3] = {(const float*)d_in[7],  (const float*)d_in[13], (const float*)d_in[19]};
    const float* W_in = (const float*)d_in[20];
    const float* b_in = (const float*)d_in[21];
    const float* Wf1  = (const float*)d_in[22];
    const float* bf1  = (const float*)d_in[23];
    const float* Wf2  = (const float*)d_in[24];
    const float* bf2  = (const float*)d_in[25];
    float* outp = (float*)d_out;

    float *p, *sA, *sB, *h, *u, *nrm, *dv;
    int* dg;
    cudaGetSymbolAddress((void**)&p,  g_p);
    cudaGetSymbolAddress((void**)&sA, g_sA);
    cudaGetSymbolAddress((void**)&sB, g_sB);
    cudaGetSymbolAddress((void**)&h,  g_h);
    cudaGetSymbolAddress((void**)&u,  g_u);
    cudaGetSymbolAddress((void**)&nrm, g_norm);
    cudaGetSymbolAddress((void**)&dv, g_dinv);
    cudaGetSymbolAddress((void**)&dg, g_deg);

    // dynamic smem sizes for the tf32 GEMM variants
    const int SMEM128 = 2 * (128 * 36 + 32 * 136) * 4;   // 71680 B
    const int SMEM64  = 2 * (128 * 36 + 32 * 72)  * 4;   // 55296 B
    cudaFuncSetAttribute(tf32_gemm<128, 0, true,  false>,
                         cudaFuncAttributeMaxDynamicSharedMemorySize, SMEM128);
    cudaFuncSetAttribute(tf32_gemm<128, 0, false, true>,
                         cudaFuncAttributeMaxDynamicSharedMemorySize, SMEM128);
    cudaFuncSetAttribute(tf32_gemm<128, 1, false, false>,
                         cudaFuncAttributeMaxDynamicSharedMemorySize, SMEM128);
    cudaFuncSetAttribute(tf32_gemm<64,  0, false, false>,
                         cudaFuncAttributeMaxDynamicSharedMemorySize, SMEM64);

    cudaMemsetAsync(dg, 0, NN * sizeof(int));
    deg_kernel<<<(EE + 255) / 256, 256>>>(dst, dg, EE);
    dinv_kernel<<<(NN + 255) / 256, 256>>>(dg, dv, NN);
    norm_kernel<<<(EE + 255) / 256, 256>>>(src, dst, dv, nrm, EE);

    const dim3 gridN256(256 / 128, (NN + 127) / 128);
    const dim3 gridN512(512 / 128, (NN + 127) / 128);
    const dim3 gridN64 (1,         (NN + 127) / 128);

    const float* hin  = x;   int din   = 128;
    const float* skip = x;   int dskip = 128;
    float* snew_arr[3] = {sA, sB, sA};

    for (int l = 0; l < 3; l++) {
        int shift = (din == 128) ? 5 : 6;
        int dq = din >> 2;
        int eTot = EE * dq;
        if (l == 0) {
            int nTot = NN * dq;
            init_p_kernel<<<(nTot + 255) / 256, 256>>>(hin, dv, p, nTot, shift);
        }
        // (for l >= 1 the previous ln_gelu already wrote p = dinv^2 * h)
        scatter_kernel<<<(eTot + 255) / 256, 256>>>(hin, src, dst, nrm, p, eTot, shift, dq - 1);
        float* snew = snew_arr[l];
        tf32_gemm<128, 0, true, false><<<gridN256, 256, SMEM128>>>(
            p, Wc[l], din, skip, Wp[l], dskip,
            bc[l], bp[l], nullptr, snew, NN, 256);
        if (l < 2) {
            ln_gelu_kernel<true><<<(NN + 7) / 8, 256>>>(snew, gn[l], be[l], h, dv, p, NN);
        } else {
            ln_gelu_kernel<false><<<(NN + 7) / 8, 256>>>(snew, gn[l], be[l], h, nullptr, nullptr, NN);
        }
        hin = h; din = 256;
        skip = snew; dskip = 256;
    }

    // t = x @ W_in + b_in + h   (sB free after layer 2 consumed it as skip)
    tf32_gemm<128, 0, false, true><<<gridN256, 256, SMEM128>>>(
        x, W_in, 128, nullptr, nullptr, 0, b_in, nullptr, h, sB, NN, 256);
    // u = gelu(t @ Wf1 + bf1)
    tf32_gemm<128, 1, false, false><<<gridN512, 256, SMEM128>>>(
        sB, Wf1, 256, nullptr, nullptr, 0, bf1, nullptr, nullptr, u, NN, 512);
    // logits = u @ Wf2 + bf2  -> d_out
    tf32_gemm<64, 0, false, false><<<gridN64, 256, SMEM64>>>(
        u, Wf2, 512, nullptr, nullptr, 0, bf2, nullptr, nullptr, outp, NN, 64);
    // in-place log_softmax
    lsm_kernel<<<(NN + 7) / 8, 256>>>(outp, NN);
}

// round 5
// speedup vs baseline: 2.3566x; 1.2388x over previous
#include <cuda_runtime.h>
#include <math.h>
#include <stdint.h>

#define NN 50000
#define EE 800000

// ---------------- device scratch (no allocation allowed) ----------------
__device__ float g_p [NN * 256];
__device__ float g_sA[NN * 256];
__device__ float g_sB[NN * 256];
__device__ float g_h [NN * 256];
__device__ float g_u [NN * 512];
__device__ float g_dinv[NN];
__device__ int   g_deg[NN];
__device__ int   g_rowptr[NN + 1];
__device__ int   g_cur[NN];
__device__ int   g_tmp[NN];
__device__ int   g_bsum[64];
__device__ int   g_csrs[EE];
__device__ float g_csrw[EE];

__device__ __forceinline__ float gelu_f(float x) {
    return 0.5f * x * (1.0f + erff(x * 0.7071067811865476f));
}

__device__ __forceinline__ uint32_t to_tf32(float x) {
    uint32_t r;
    asm("cvt.rna.tf32.f32 %0, %1;\n" : "=r"(r) : "f"(x));
    return r;
}

// ---------------- degree / dinv ----------------
__global__ void deg_kernel(const int* __restrict__ dst, int* __restrict__ deg, int E) {
    int e = blockIdx.x * blockDim.x + threadIdx.x;
    if (e < E) atomicAdd(&deg[dst[e]], 1);
}

__global__ void dinv_kernel(const int* __restrict__ deg, float* __restrict__ dinv, int n) {
    int i = blockIdx.x * blockDim.x + threadIdx.x;
    if (i < n) dinv[i] = rsqrtf((float)deg[i] + 1.0f);
}

// ---------------- 3-kernel exclusive scan of deg -> rowptr ----------------
__global__ void scan_blk(const int* __restrict__ deg, int* __restrict__ tmp,
                         int* __restrict__ bsum, int n) {
    __shared__ int s[1024];
    int i = blockIdx.x * 1024 + threadIdx.x;
    int v = (i < n) ? deg[i] : 0;
    s[threadIdx.x] = v;
    __syncthreads();
#pragma unroll
    for (int o = 1; o < 1024; o <<= 1) {
        int t = (threadIdx.x >= o) ? s[threadIdx.x - o] : 0;
        __syncthreads();
        s[threadIdx.x] += t;
        __syncthreads();
    }
    if (i < n) tmp[i] = s[threadIdx.x];
    if (threadIdx.x == 1023) bsum[blockIdx.x] = s[1023];
}

__global__ void scan_top(int* __restrict__ bsum, int nb) {
    __shared__ int s[64];
    int v = (threadIdx.x < nb) ? bsum[threadIdx.x] : 0;
    s[threadIdx.x] = v;
    __syncthreads();
#pragma unroll
    for (int o = 1; o < 64; o <<= 1) {
        int t = (threadIdx.x >= o) ? s[threadIdx.x - o] : 0;
        __syncthreads();
        s[threadIdx.x] += t;
        __syncthreads();
    }
    if (threadIdx.x < nb) bsum[threadIdx.x] = s[threadIdx.x];
}

__global__ void scan_add(const int* __restrict__ tmp, const int* __restrict__ bsum,
                         int* __restrict__ rowptr, int* __restrict__ cur, int n) {
    int i = blockIdx.x * blockDim.x + threadIdx.x;
    if (i > n) return;
    int v;
    if (i == 0) v = 0;
    else {
        int j = i - 1;
        v = tmp[j] + ((j >= 1024) ? bsum[j / 1024 - 1] : 0);
    }
    rowptr[i] = v;
    if (i < n) cur[i] = v;
}

// ---------------- CSR bucket fill (also computes edge weights) ----------------
__global__ void fill_kernel(const int* __restrict__ src, const int* __restrict__ dst,
                            const float* __restrict__ dinv, int* __restrict__ cur,
                            int* __restrict__ csrs, float* __restrict__ csrw, int E) {
    int e = blockIdx.x * blockDim.x + threadIdx.x;
    if (e >= E) return;
    int s = src[e], d = dst[e];
    int pos = atomicAdd(&cur[d], 1);
    csrs[pos] = s;
    csrw[pos] = dinv[s] * dinv[d];
}

// ---------------- CSR gather: p[row] = dinv[row]^2*h[row] + sum_j w_j*h[src_j] ----
// One block per node: NG neighbor-groups x LANES channel-lanes (float4 each).
template<int D>
__global__ __launch_bounds__(256)
void gather_kernel(const float* __restrict__ h, const float* __restrict__ dinv,
                   const int* __restrict__ rowptr, const int* __restrict__ csrs,
                   const float* __restrict__ csrw, float* __restrict__ p) {
    constexpr int LANES = D / 4;        // 32 or 64
    constexpr int NG = 256 / LANES;     // 8 or 4
    constexpr int CH = 256;
    __shared__ int   s_src[CH];
    __shared__ float s_w[CH];
    __shared__ float4 s_red[256];

    const int row  = blockIdx.x;
    const int tid  = threadIdx.x;
    const int lane = tid % LANES;
    const int ng   = tid / LANES;
    const int start = rowptr[row];
    const int end   = rowptr[row + 1];

    float4 acc = make_float4(0.f, 0.f, 0.f, 0.f);
    if (ng == 0) {
        float w = dinv[row]; w = w * w;
        float4 v = *(const float4*)(h + (size_t)row * D + lane * 4);
        acc = make_float4(v.x * w, v.y * w, v.z * w, v.w * w);
    }
    for (int base = start; base < end; base += CH) {
        int cnt = min(CH, end - base);
        for (int j = tid; j < cnt; j += 256) {
            s_src[j] = csrs[base + j];
            s_w[j]   = csrw[base + j];
        }
        __syncthreads();
        for (int j = ng; j < cnt; j += NG) {
            float w = s_w[j];
            const float4 v = *(const float4*)(h + (size_t)s_src[j] * D + lane * 4);
            acc.x += w * v.x; acc.y += w * v.y;
            acc.z += w * v.z; acc.w += w * v.w;
        }
        __syncthreads();
    }
    s_red[tid] = acc;
    __syncthreads();
    if (ng == 0) {
#pragma unroll
        for (int g = 1; g < NG; g++) {
            float4 o = s_red[g * LANES + lane];
            acc.x += o.x; acc.y += o.y; acc.z += o.z; acc.w += o.w;
        }
        *(float4*)(p + (size_t)row * D + lane * 4) = acc;
    }
}

// ---------------- tf32 tensor-core GEMM ----------------
// out = act( A1@W1 [+ A2@W2] + b1 [+ b2] [+ addM] ), row-major. K % 32 == 0.
// BM=128, BN in {128,64}, BK=32, 256 threads (8 warps, 4x2),
// warp tile 32 x (BN/2). cp.async double-buffered dynamic smem.
template<int BN, int ACT, bool DUAL, bool ADDM>
__global__ __launch_bounds__(256)
void tf32_gemm(const float* __restrict__ A1, const float* __restrict__ W1, int K1,
               const float* __restrict__ A2, const float* __restrict__ W2, int K2,
               const float* __restrict__ b1, const float* __restrict__ b2,
               const float* __restrict__ addM, float* __restrict__ out,
               int M, int NC) {
    constexpr int BM = 128, BK = 32;
    constexpr int ASTR = 36;
    constexpr int BSTR = BN + 8;
    constexpr int AFL  = BM * ASTR;
    constexpr int BFL  = BK * BSTR;
    constexpr int BUFF = AFL + BFL;
    constexpr int NT   = BN / 16;

    extern __shared__ float smem[];

    const int tid  = threadIdx.x;
    const int lane = tid & 31;
    const int warp = tid >> 5;
    const int wm   = warp & 3;
    const int wn   = warp >> 2;
    const int gid  = lane >> 2;
    const int tig  = lane & 3;
    const int rowBase = blockIdx.y * BM;
    const int colBase = blockIdx.x * BN;

    const uint32_t sbase = (uint32_t)__cvta_generic_to_shared(smem);

    float acc[2][NT][4];
#pragma unroll
    for (int mt = 0; mt < 2; mt++)
#pragma unroll
        for (int nt = 0; nt < NT; nt++)
#pragma unroll
            for (int i = 0; i < 4; i++) acc[mt][nt][i] = 0.0f;

    const int nPhase = DUAL ? 2 : 1;
    for (int phase = 0; phase < nPhase; ++phase) {
        const float* A = (phase == 0) ? A1 : A2;
        const float* W = (phase == 0) ? W1 : W2;
        const int K    = (phase == 0) ? K1 : K2;
        const int nTiles = K / BK;

        auto cpTile = [&](int t, int b) {
            const int k0 = t * BK;
            const uint32_t aoff = sbase + (uint32_t)(b * BUFF) * 4u;
            const uint32_t boff = aoff + (uint32_t)AFL * 4u;
#pragma unroll
            for (int i = 0; i < 4; i++) {
                int idx = tid + i * 256;
                int r   = idx >> 3;
                int c4  = (idx & 7) << 2;
                int grow = rowBase + r;
                int sz = (grow < M) ? 16 : 0;
                const float* g = A + (size_t)((grow < M) ? grow : 0) * K + k0 + c4;
                uint32_t sa = aoff + (uint32_t)(r * ASTR + c4) * 4u;
                asm volatile("cp.async.ca.shared.global [%0], [%1], 16, %2;\n"
                             :: "r"(sa), "l"(g), "r"(sz));
            }
            constexpr int BI = (BN == 128) ? 4 : 2;
#pragma unroll
            for (int i = 0; i < BI; i++) {
                int idx = tid + i * 256;
                int r   = idx >> ((BN == 128) ? 5 : 4);
                int c4  = (idx & ((BN / 4) - 1)) << 2;
                const float* g = W + (size_t)(k0 + r) * NC + colBase + c4;
                uint32_t sa = boff + (uint32_t)(r * BSTR + c4) * 4u;
                asm volatile("cp.async.ca.shared.global [%0], [%1], 16, %2;\n"
                             :: "r"(sa), "l"(g), "r"(16));
            }
            asm volatile("cp.async.commit_group;\n" ::);
        };

        int buf = 0;
        cpTile(0, 0);
        for (int t = 0; t < nTiles; t++) {
            const bool hasNext = (t + 1) < nTiles;
            if (hasNext) {
                cpTile(t + 1, buf ^ 1);
                asm volatile("cp.async.wait_group 1;\n" ::);
            } else {
                asm volatile("cp.async.wait_group 0;\n" ::);
            }
            __syncthreads();

            const float* As = smem + buf * BUFF;
            const float* Bs = As + AFL;
#pragma unroll
            for (int ks = 0; ks < 4; ks++) {
                const int k = ks * 8;
                uint32_t a[2][4];
                uint32_t b[NT][2];
#pragma unroll
                for (int mt = 0; mt < 2; mt++) {
                    int m = wm * 32 + mt * 16 + gid;
                    a[mt][0] = to_tf32(As[m * ASTR + k + tig]);
                    a[mt][1] = to_tf32(As[(m + 8) * ASTR + k + tig]);
                    a[mt][2] = to_tf32(As[m * ASTR + k + tig + 4]);
                    a[mt][3] = to_tf32(As[(m + 8) * ASTR + k + tig + 4]);
                }
#pragma unroll
                for (int nt = 0; nt < NT; nt++) {
                    int n = wn * (BN / 2) + nt * 8 + gid;
                    b[nt][0] = to_tf32(Bs[(k + tig) * BSTR + n]);
                    b[nt][1] = to_tf32(Bs[(k + tig + 4) * BSTR + n]);
                }
#pragma unroll
                for (int mt = 0; mt < 2; mt++)
#pragma unroll
                    for (int nt = 0; nt < NT; nt++) {
                        asm volatile(
                            "mma.sync.aligned.m16n8k8.row.col.f32.tf32.tf32.f32 "
                            "{%0,%1,%2,%3}, {%4,%5,%6,%7}, {%8,%9}, {%0,%1,%2,%3};\n"
                            : "+f"(acc[mt][nt][0]), "+f"(acc[mt][nt][1]),
                              "+f"(acc[mt][nt][2]), "+f"(acc[mt][nt][3])
                            : "r"(a[mt][0]), "r"(a[mt][1]), "r"(a[mt][2]), "r"(a[mt][3]),
                              "r"(b[nt][0]), "r"(b[nt][1]));
                    }
            }
            __syncthreads();
            buf ^= 1;
        }
    }

    // ---------------- epilogue ----------------
#pragma unroll
    for (int mt = 0; mt < 2; mt++) {
        const int r0 = rowBase + wm * 32 + mt * 16 + gid;
        const int r1 = r0 + 8;
#pragma unroll
        for (int nt = 0; nt < NT; nt++) {
            const int cn = colBase + wn * (BN / 2) + nt * 8 + tig * 2;
            float bias0 = b1[cn], bias1 = b1[cn + 1];
            if (DUAL) { bias0 += b2[cn]; bias1 += b2[cn + 1]; }
            float v0 = acc[mt][nt][0] + bias0;
            float v1 = acc[mt][nt][1] + bias1;
            float v2 = acc[mt][nt][2] + bias0;
            float v3 = acc[mt][nt][3] + bias1;
            if (r0 < M) {
                if (ADDM) {
                    float2 m0 = *(const float2*)(addM + (size_t)r0 * NC + cn);
                    v0 += m0.x; v1 += m0.y;
                }
                if (ACT == 1) { v0 = gelu_f(v0); v1 = gelu_f(v1); }
                *(float2*)(out + (size_t)r0 * NC + cn) = make_float2(v0, v1);
            }
            if (r1 < M) {
                if (ADDM) {
                    float2 m1 = *(const float2*)(addM + (size_t)r1 * NC + cn);
                    v2 += m1.x; v3 += m1.y;
                }
                if (ACT == 1) { v2 = gelu_f(v2); v3 = gelu_f(v3); }
                *(float2*)(out + (size_t)r1 * NC + cn) = make_float2(v2, v3);
            }
        }
    }
}

// ------- LayerNorm(d=256) + GELU, warp per row ----------------
__global__ void ln_gelu_kernel(const float* __restrict__ in, const float* __restrict__ g,
                               const float* __restrict__ be, float* __restrict__ out,
                               int M) {
    int warp = blockIdx.x * 8 + (threadIdx.x >> 5);
    int lane = threadIdx.x & 31;
    if (warp >= M) return;
    const float* row = in + (size_t)warp * 256;
    float4 a = *(const float4*)(row + lane * 4);
    float4 b = *(const float4*)(row + 128 + lane * 4);
    float s = a.x + a.y + a.z + a.w + b.x + b.y + b.z + b.w;
#pragma unroll
    for (int o = 16; o; o >>= 1) s += __shfl_xor_sync(0xffffffffu, s, o);
    float mean = s * (1.0f / 256.0f);
    float d, v = 0.f;
    d = a.x - mean; v += d * d;  d = a.y - mean; v += d * d;
    d = a.z - mean; v += d * d;  d = a.w - mean; v += d * d;
    d = b.x - mean; v += d * d;  d = b.y - mean; v += d * d;
    d = b.z - mean; v += d * d;  d = b.w - mean; v += d * d;
#pragma unroll
    for (int o = 16; o; o >>= 1) v += __shfl_xor_sync(0xffffffffu, v, o);
    float rstd = rsqrtf(v * (1.0f / 256.0f) + 1e-5f);

    int c0 = lane * 4, c1 = 128 + lane * 4;
    float4 g0 = *(const float4*)(g + c0),  g1 = *(const float4*)(g + c1);
    float4 e0 = *(const float4*)(be + c0), e1 = *(const float4*)(be + c1);
    float4 o0, o1;
    o0.x = gelu_f((a.x - mean) * rstd * g0.x + e0.x);
    o0.y = gelu_f((a.y - mean) * rstd * g0.y + e0.y);
    o0.z = gelu_f((a.z - mean) * rstd * g0.z + e0.z);
    o0.w = gelu_f((a.w - mean) * rstd * g0.w + e0.w);
    o1.x = gelu_f((b.x - mean) * rstd * g1.x + e1.x);
    o1.y = gelu_f((b.y - mean) * rstd * g1.y + e1.y);
    o1.z = gelu_f((b.z - mean) * rstd * g1.z + e1.z);
    o1.w = gelu_f((b.w - mean) * rstd * g1.w + e1.w);
    float* orow = out + (size_t)warp * 256;
    *(float4*)(orow + lane * 4)       = o0;
    *(float4*)(orow + 128 + lane * 4) = o1;
}

// ---------------- log_softmax over 64 cols, warp per row, in-place ----------------
__global__ void lsm_kernel(float* __restrict__ io, int M) {
    int warp = blockIdx.x * 8 + (threadIdx.x >> 5);
    int lane = threadIdx.x & 31;
    if (warp >= M) return;
    float* row = io + (size_t)warp * 64;
    float2 v = *(float2*)(row + lane * 2);
    float m = fmaxf(v.x, v.y);
#pragma unroll
    for (int o = 16; o; o >>= 1) m = fmaxf(m, __shfl_xor_sync(0xffffffffu, m, o));
    float s = expf(v.x - m) + expf(v.y - m);
#pragma unroll
    for (int o = 16; o; o >>= 1) s += __shfl_xor_sync(0xffffffffu, s, o);
    float l = m + logf(s);
    v.x -= l; v.y -= l;
    *(float2*)(row + lane * 2) = v;
}

// ---------------- host orchestration ----------------
extern "C" void kernel_launch(void* const* d_in, const int* in_sizes, int n_in,
                              void* d_out, int out_size) {
    const float* x   = (const float*)d_in[0];
    const int*   ei  = (const int*)d_in[1];
    const int*   src = ei;
    const int*   dst = ei + EE;
    const float* Wc[3] = {(const float*)d_in[2],  (const float*)d_in[8],  (const float*)d_in[14]};
    const float* bc[3] = {(const float*)d_in[3],  (const float*)d_in[9],  (const float*)d_in[15]};
    const float* Wp[3] = {(const float*)d_in[4],  (const float*)d_in[10], (const float*)d_in[16]};
    const float* bp[3] = {(const float*)d_in[5],  (const float*)d_in[11], (const float*)d_in[17]};
    const float* gn[3] = {(const float*)d_in[6],  (const float*)d_in[12], (const float*)d_in[18]};
    const float* be[3] = {(const float*)d_in[7],  (const float*)d_in[13], (const float*)d_in[19]};
    const float* W_in = (const float*)d_in[20];
    const float* b_in = (const float*)d_in[21];
    const float* Wf1  = (const float*)d_in[22];
    const float* bf1  = (const float*)d_in[23];
    const float* Wf2  = (const float*)d_in[24];
    const float* bf2  = (const float*)d_in[25];
    float* outp = (float*)d_out;

    float *p, *sA, *sB, *h, *u, *dv, *csrw;
    int *dg, *rowptr, *cur, *tmp, *bsum, *csrs;
    cudaGetSymbolAddress((void**)&p,  g_p);
    cudaGetSymbolAddress((void**)&sA, g_sA);
    cudaGetSymbolAddress((void**)&sB, g_sB);
    cudaGetSymbolAddress((void**)&h,  g_h);
    cudaGetSymbolAddress((void**)&u,  g_u);
    cudaGetSymbolAddress((void**)&dv, g_dinv);
    cudaGetSymbolAddress((void**)&dg, g_deg);
    cudaGetSymbolAddress((void**)&rowptr, g_rowptr);
    cudaGetSymbolAddress((void**)&cur, g_cur);
    cudaGetSymbolAddress((void**)&tmp, g_tmp);
    cudaGetSymbolAddress((void**)&bsum, g_bsum);
    cudaGetSymbolAddress((void**)&csrs, g_csrs);
    cudaGetSymbolAddress((void**)&csrw, g_csrw);

    const int SMEM128 = 2 * (128 * 36 + 32 * 136) * 4;   // 71680 B
    const int SMEM64  = 2 * (128 * 36 + 32 * 72)  * 4;   // 55296 B
    cudaFuncSetAttribute(tf32_gemm<128, 0, true,  false>,
                         cudaFuncAttributeMaxDynamicSharedMemorySize, SMEM128);
    cudaFuncSetAttribute(tf32_gemm<128, 0, false, true>,
                         cudaFuncAttributeMaxDynamicSharedMemorySize, SMEM128);
    cudaFuncSetAttribute(tf32_gemm<128, 1, false, false>,
                         cudaFuncAttributeMaxDynamicSharedMemorySize, SMEM128);
    cudaFuncSetAttribute(tf32_gemm<64,  0, false, false>,
                         cudaFuncAttributeMaxDynamicSharedMemorySize, SMEM64);

    // ---- CSR build ----
    const int NB = (NN + 1023) / 1024;   // 49
    cudaMemsetAsync(dg, 0, NN * sizeof(int));
    deg_kernel<<<(EE + 255) / 256, 256>>>(dst, dg, EE);
    dinv_kernel<<<(NN + 255) / 256, 256>>>(dg, dv, NN);
    scan_blk<<<NB, 1024>>>(dg, tmp, bsum, NN);
    scan_top<<<1, 64>>>(bsum, NB);
    scan_add<<<(NN + 1 + 255) / 256, 256>>>(tmp, bsum, rowptr, cur, NN);
    fill_kernel<<<(EE + 255) / 256, 256>>>(src, dst, dv, cur, csrs, csrw, EE);

    const dim3 gridN256(256 / 128, (NN + 127) / 128);
    const dim3 gridN512(512 / 128, (NN + 127) / 128);
    const dim3 gridN64 (1,         (NN + 127) / 128);

    const float* hin  = x;   int din   = 128;
    const float* skip = x;   int dskip = 128;
    float* snew_arr[3] = {sA, sB, sA};

    for (int l = 0; l < 3; l++) {
        if (din == 128)
            gather_kernel<128><<<NN, 256>>>(hin, dv, rowptr, csrs, csrw, p);
        else
            gather_kernel<256><<<NN, 256>>>(hin, dv, rowptr, csrs, csrw, p);
        float* snew = snew_arr[l];
        tf32_gemm<128, 0, true, false><<<gridN256, 256, SMEM128>>>(
            p, Wc[l], din, skip, Wp[l], dskip,
            bc[l], bp[l], nullptr, snew, NN, 256);
        ln_gelu_kernel<<<(NN + 7) / 8, 256>>>(snew, gn[l], be[l], h, NN);
        hin = h; din = 256;
        skip = snew; dskip = 256;
    }

    // t = x @ W_in + b_in + h   (sB free after layer 2 consumed it as skip)
    tf32_gemm<128, 0, false, true><<<gridN256, 256, SMEM128>>>(
        x, W_in, 128, nullptr, nullptr, 0, b_in, nullptr, h, sB, NN, 256);
    // u = gelu(t @ Wf1 + bf1)
    tf32_gemm<128, 1, false, false><<<gridN512, 256, SMEM128>>>(
        sB, Wf1, 256, nullptr, nullptr, 0, bf1, nullptr, nullptr, u, NN, 512);
    // logits = u @ Wf2 + bf2  -> d_out
    tf32_gemm<64, 0, false, false><<<gridN64, 256, SMEM64>>>(
        u, Wf2, 512, nullptr, nullptr, 0, bf2, nullptr, nullptr, outp, NN, 64);
    // in-place log_softmax
    lsm_kernel<<<(NN + 7) / 8, 256>>>(outp, NN);
}

// round 7
// speedup vs baseline: 2.7459x; 1.1652x over previous
#include <cuda_runtime.h>
#include <cuda_bf16.h>
#include <math.h>
#include <stdint.h>

#define NN 50000
#define EE 800000

typedef __nv_bfloat16 bf16;
typedef __nv_bfloat162 bf162;

// ---------------- device scratch (no allocation allowed) ----------------
__device__ __align__(256) bf16  g_p [NN * 256];
__device__ __align__(256) bf16  g_sA[NN * 256];
__device__ __align__(256) bf16  g_sB[NN * 256];
__device__ __align__(256) bf16  g_h [NN * 256];
__device__ __align__(256) bf16  g_u [NN * 512];
__device__ __align__(256) bf16  g_xb[NN * 128];
__device__ __align__(256) unsigned g_wpack[262144];
__device__ float g_dinv[NN];
__device__ int   g_deg[NN];
__device__ int   g_rowptr[NN + 1];
__device__ int   g_cur[NN];
__device__ int   g_tmp[NN];
__device__ int   g_bsum[64];
__device__ int   g_csrs[EE];
__device__ float g_csrw[EE];

__device__ __forceinline__ float gelu_f(float x) {
    return 0.5f * x * (1.0f + erff(x * 0.7071067811865476f));
}

// ---------------- weight pack / x convert ----------------
struct PackSeg { const float* src; unsigned* dst; int ncols; int mode; unsigned count; };
struct PackArgs { PackSeg seg[10]; unsigned total; };

__global__ void pack_kernel(PackArgs pa) {
    unsigned u = blockIdx.x * 256 + threadIdx.x;
    if (u >= pa.total) return;
    int s = 0; unsigned base = 0;
    while (u >= base + pa.seg[s].count) { base += pa.seg[s].count; s++; }
    unsigned i = u - base;
    const float* src = pa.seg[s].src;
    float lo, hi;
    if (pa.seg[s].mode == 0) {
        int N = pa.seg[s].ncols;
        unsigned kp = i / N, n = i % N;
        lo = src[(size_t)(2 * kp) * N + n];
        hi = src[(size_t)(2 * kp + 1) * N + n];
    } else {
        lo = src[2 * (size_t)i];
        hi = src[2 * (size_t)i + 1];
    }
    bf162 h2 = __float22bfloat162_rn(make_float2(lo, hi));
    pa.seg[s].dst[i] = *(unsigned*)&h2;
}

// ---------------- degree / dinv ----------------
__global__ void deg_kernel(const int* __restrict__ dst, int* __restrict__ deg, int E) {
    int e = blockIdx.x * blockDim.x + threadIdx.x;
    if (e < E) atomicAdd(&deg[dst[e]], 1);
}

__global__ void dinv_kernel(const int* __restrict__ deg, float* __restrict__ dinv, int n) {
    int i = blockIdx.x * blockDim.x + threadIdx.x;
    if (i < n) dinv[i] = rsqrtf((float)deg[i] + 1.0f);
}

// ---------------- 3-kernel exclusive scan of deg -> rowptr ----------------
__global__ void scan_blk(const int* __restrict__ deg, int* __restrict__ tmp,
                         int* __restrict__ bsum, int n) {
    __shared__ int s[1024];
    int i = blockIdx.x * 1024 + threadIdx.x;
    int v = (i < n) ? deg[i] : 0;
    s[threadIdx.x] = v;
    __syncthreads();
#pragma unroll
    for (int o = 1; o < 1024; o <<= 1) {
        int t = (threadIdx.x >= o) ? s[threadIdx.x - o] : 0;
        __syncthreads();
        s[threadIdx.x] += t;
        __syncthreads();
    }
    if (i < n) tmp[i] = s[threadIdx.x];
    if (threadIdx.x == 1023) bsum[blockIdx.x] = s[1023];
}

__global__ void scan_top(int* __restrict__ bsum, int nb) {
    __shared__ int s[64];
    int v = (threadIdx.x < nb) ? bsum[threadIdx.x] : 0;
    s[threadIdx.x] = v;
    __syncthreads();
#pragma unroll
    for (int o = 1; o < 64; o <<= 1) {
        int t = (threadIdx.x >= o) ? s[threadIdx.x - o] : 0;
        __syncthreads();
        s[threadIdx.x] += t;
        __syncthreads();
    }
    if (threadIdx.x < nb) bsum[threadIdx.x] = s[threadIdx.x];
}

__global__ void scan_add(const int* __restrict__ tmp, const int* __restrict__ bsum,
                         int* __restrict__ rowptr, int* __restrict__ cur, int n) {
    int i = blockIdx.x * blockDim.x + threadIdx.x;
    if (i > n) return;
    int v;
    if (i == 0) v = 0;
    else {
        int j = i - 1;
        v = tmp[j] + ((j >= 1024) ? bsum[j / 1024 - 1] : 0);
    }
    rowptr[i] = v;
    if (i < n) cur[i] = v;
}

// ---------------- CSR bucket fill (also computes edge weights) ----------------
__global__ void fill_kernel(const int* __restrict__ src, const int* __restrict__ dst,
                            const float* __restrict__ dinv, int* __restrict__ cur,
                            int* __restrict__ csrs, float* __restrict__ csrw, int E) {
    int e = blockIdx.x * blockDim.x + threadIdx.x;
    if (e >= E) return;
    int s = src[e], d = dst[e];
    int pos = atomicAdd(&cur[d], 1);
    csrs[pos] = s;
    csrw[pos] = dinv[s] * dinv[d];
}

// ---------------- CSR gather (bf16 in / bf16 out, fp32 accumulate) ----------
// p[row] = dinv[row]^2*h[row] + sum_j w_j*h[src_j]
template<int D>
__global__ __launch_bounds__(256)
void gather_kernel(const bf16* __restrict__ h, const float* __restrict__ dinv,
                   const int* __restrict__ rowptr, const int* __restrict__ csrs,
                   const float* __restrict__ csrw, bf16* __restrict__ p) {
    constexpr int LANES = D / 8;        // 16 or 32 (8 halves per lane)
    constexpr int NG = 256 / LANES;     // 16 or 8
    constexpr int CH = 256;
    __shared__ int   s_src[CH];
    __shared__ float s_w[CH];
    __shared__ float s_red[256 * 8];

    const int row  = blockIdx.x;
    const int tid  = threadIdx.x;
    const int lane = tid % LANES;
    const int ng   = tid / LANES;
    const int start = rowptr[row];
    const int end   = rowptr[row + 1];

    float acc[8];
#pragma unroll
    for (int c = 0; c < 8; c++) acc[c] = 0.f;

    if (ng == 0) {
        float w = dinv[row]; w = w * w;
        uint4 q = *(const uint4*)(h + (size_t)row * D + lane * 8);
        const bf162* b2 = (const bf162*)&q;
#pragma unroll
        for (int c = 0; c < 4; c++) {
            float2 f = __bfloat1622float2(b2[c]);
            acc[2 * c]     = w * f.x;
            acc[2 * c + 1] = w * f.y;
        }
    }
    for (int base = start; base < end; base += CH) {
        int cnt = min(CH, end - base);
        for (int j = tid; j < cnt; j += 256) {
            s_src[j] = csrs[base + j];
            s_w[j]   = csrw[base + j];
        }
        __syncthreads();
        for (int j = ng; j < cnt; j += NG) {
            float w = s_w[j];
            uint4 q = *(const uint4*)(h + (size_t)s_src[j] * D + lane * 8);
            const bf162* b2 = (const bf162*)&q;
#pragma unroll
            for (int c = 0; c < 4; c++) {
                float2 f = __bfloat1622float2(b2[c]);
                acc[2 * c]     += w * f.x;
                acc[2 * c + 1] += w * f.y;
            }
        }
        __syncthreads();
    }
#pragma unroll
    for (int c = 0; c < 8; c++) s_red[tid * 8 + c] = acc[c];
    __syncthreads();
    if (ng == 0) {
#pragma unroll
        for (int g = 1; g < NG; g++)
#pragma unroll
            for (int c = 0; c < 8; c++)
                acc[c] += s_red[(g * LANES + lane) * 8 + c];
        uint4 o;
        bf162* ob = (bf162*)&o;
#pragma unroll
        for (int c = 0; c < 4; c++)
            ob[c] = __float22bfloat162_rn(make_float2(acc[2 * c], acc[2 * c + 1]));
        *(uint4*)(p + (size_t)row * D + lane * 8) = o;
    }
}

// ---------------- bf16 tensor-core GEMM (m16n8k16) ----------------
// out = act( A1@W1 [+ A2@W2] + b1 [+ b2] [+ addM] ). K % 32 == 0.
// A: bf16 row-major [M][K]. W: packed u32 [K/2][NC] (k-pairs).
// BM=128, BN in {128,64}, BK=32 (halves), 256 threads, warp tile 32 x BN/2.
template<int BN, int ACT, bool DUAL, bool ADDM, bool OUTBF>
__global__ __launch_bounds__(256)
void bf16_gemm(const bf16* __restrict__ A1, const unsigned* __restrict__ W1, int K1,
               const bf16* __restrict__ A2, const unsigned* __restrict__ W2, int K2,
               const float* __restrict__ b1, const float* __restrict__ b2,
               const bf16* __restrict__ addM, void* __restrict__ outv,
               int M, int NC) {
    constexpr int BM = 128;
    constexpr int ASTR = 20;                // A smem row stride (u32): 20g+t distinct mod 32
    constexpr int BSTR = BN + 8;            // B smem row stride (u32): ≡8 mod 32
    constexpr int AU  = BM * ASTR;          // u32 per A buffer
    constexpr int BU  = 16 * BSTR;          // 16 kp-rows
    constexpr int BUFF = AU + BU;
    constexpr int NT  = BN / 16;            // n-tiles per warp (8 cols each)

    extern __shared__ __align__(16) unsigned smem[];

    const int tid  = threadIdx.x;
    const int lane = tid & 31;
    const int warp = tid >> 5;
    const int wm   = warp & 3;
    const int wn   = warp >> 2;
    const int gid  = lane >> 2;
    const int tig  = lane & 3;
    const int rowBase = blockIdx.y * BM;
    const int colBase = blockIdx.x * BN;

    const uint32_t sbase = (uint32_t)__cvta_generic_to_shared(smem);

    float acc[2][NT][4];
#pragma unroll
    for (int mt = 0; mt < 2; mt++)
#pragma unroll
        for (int nt = 0; nt < NT; nt++)
#pragma unroll
            for (int i = 0; i < 4; i++) acc[mt][nt][i] = 0.0f;

    const int nPhase = DUAL ? 2 : 1;
    for (int phase = 0; phase < nPhase; ++phase) {
        const bf16* A     = (phase == 0) ? A1 : A2;
        const unsigned* W = (phase == 0) ? W1 : W2;
        const int K       = (phase == 0) ? K1 : K2;
        const int nTiles  = K / 32;

        auto cpTile = [&](int t, int b) {
            const int k0 = t * 32;          // in bf16 elements
            const uint32_t aoff = sbase + (uint32_t)(b * BUFF) * 4u;
            const uint32_t boff = aoff + (uint32_t)AU * 4u;
            // A: 128 rows x 16 u32 = 512 16B-chunks
#pragma unroll
            for (int i = 0; i < 2; i++) {
                int idx = tid + i * 256;
                int r   = idx >> 2;
                int c4  = (idx & 3) << 2;       // u32 offset within row
                int grow = rowBase + r;
                int sz = (grow < M) ? 16 : 0;
                const bf16* g = A + (size_t)((grow < M) ? grow : 0) * K + k0 + 2 * c4;
                uint32_t sa = aoff + (uint32_t)(r * ASTR + c4) * 4u;
                asm volatile("cp.async.ca.shared.global [%0], [%1], 16, %2;\n"
                             :: "r"(sa), "l"(g), "r"(sz));
            }
            // B: 16 kp-rows x BN u32
            constexpr int BI = (BN == 128) ? 2 : 1;
#pragma unroll
            for (int i = 0; i < BI; i++) {
                int idx = tid + i * 256;
                int r   = idx >> ((BN == 128) ? 5 : 4);
                int c4  = (idx & ((BN / 4) - 1)) << 2;
                const unsigned* g = W + (size_t)(k0 / 2 + r) * NC + colBase + c4;
                uint32_t sa = boff + (uint32_t)(r * BSTR + c4) * 4u;
                asm volatile("cp.async.ca.shared.global [%0], [%1], 16, %2;\n"
                             :: "r"(sa), "l"(g), "r"(16));
            }
            asm volatile("cp.async.commit_group;\n" ::);
        };

        int buf = 0;
        cpTile(0, 0);
        for (int t = 0; t < nTiles; t++) {
            const bool hasNext = (t + 1) < nTiles;
            if (hasNext) {
                cpTile(t + 1, buf ^ 1);
                asm volatile("cp.async.wait_group 1;\n" ::);
            } else {
                asm volatile("cp.async.wait_group 0;\n" ::);
            }
            __syncthreads();

            const unsigned* As = smem + buf * BUFF;
            const unsigned* Bs = As + AU;
#pragma unroll
            for (int ks = 0; ks < 2; ks++) {
                const int kb = ks * 8;          // u32 col base (A) / kp row base (B)
                unsigned a[2][4];
                unsigned b[NT][2];
#pragma unroll
                for (int mt = 0; mt < 2; mt++) {
                    int m = wm * 32 + mt * 16 + gid;
                    a[mt][0] = As[m * ASTR + kb + tig];
                    a[mt][1] = As[(m + 8) * ASTR + kb + tig];
                    a[mt][2] = As[m * ASTR + kb + tig + 4];
                    a[mt][3] = As[(m + 8) * ASTR + kb + tig + 4];
                }
#pragma unroll
                for (int nt = 0; nt < NT; nt++) {
                    int n = wn * (BN / 2) + nt * 8 + gid;
                    b[nt][0] = Bs[(kb + tig) * BSTR + n];
                    b[nt][1] = Bs[(kb + tig + 4) * BSTR + n];
                }
#pragma unroll
                for (int mt = 0; mt < 2; mt++)
#pragma unroll
                    for (int nt = 0; nt < NT; nt++) {
                        asm volatile(
                            "mma.sync.aligned.m16n8k16.row.col.f32.bf16.bf16.f32 "
                            "{%0,%1,%2,%3}, {%4,%5,%6,%7}, {%8,%9}, {%0,%1,%2,%3};\n"
                            : "+f"(acc[mt][nt][0]), "+f"(acc[mt][nt][1]),
                              "+f"(acc[mt][nt][2]), "+f"(acc[mt][nt][3])
                            : "r"(a[mt][0]), "r"(a[mt][1]), "r"(a[mt][2]), "r"(a[mt][3]),
                              "r"(b[nt][0]), "r"(b[nt][1]));
                    }
            }
            __syncthreads();
            buf ^= 1;
        }
    }

    // ---------------- epilogue ----------------
#pragma unroll
    for (int mt = 0; mt < 2; mt++) {
        const int r0 = rowBase + wm * 32 + mt * 16 + gid;
        const int r1 = r0 + 8;
#pragma unroll
        for (int nt = 0; nt < NT; nt++) {
            const int cn = colBase + wn * (BN / 2) + nt * 8 + tig * 2;
            float bias0 = b1[cn], bias1 = b1[cn + 1];
            if (DUAL) { bias0 += b2[cn]; bias1 += b2[cn + 1]; }
            float v0 = acc[mt][nt][0] + bias0;
            float v1 = acc[mt][nt][1] + bias1;
            float v2 = acc[mt][nt][2] + bias0;
            float v3 = acc[mt][nt][3] + bias1;
            if (r0 < M) {
                if (ADDM) {
                    unsigned q = *(const unsigned*)(addM + (size_t)r0 * NC + cn);
                    float2 f = __bfloat1622float2(*(const bf162*)&q);
                    v0 += f.x; v1 += f.y;
                }
                if (ACT == 1) { v0 = gelu_f(v0); v1 = gelu_f(v1); }
                if (OUTBF) {
                    bf162 o = __float22bfloat162_rn(make_float2(v0, v1));
                    *(unsigned*)((bf16*)outv + (size_t)r0 * NC + cn) = *(unsigned*)&o;
                } else {
                    *(float2*)((float*)outv + (size_t)r0 * NC + cn) = make_float2(v0, v1);
                }
            }
            if (r1 < M) {
                if (ADDM) {
                    unsigned q = *(const unsigned*)(addM + (size_t)r1 * NC + cn);
                    float2 f = __bfloat1622float2(*(const bf162*)&q);
                    v2 += f.x; v3 += f.y;
                }
                if (ACT == 1) { v2 = gelu_f(v2); v3 = gelu_f(v3); }
                if (OUTBF) {
                    bf162 o = __float22bfloat162_rn(make_float2(v2, v3));
                    *(unsigned*)((bf16*)outv + (size_t)r1 * NC + cn) = *(unsigned*)&o;
                } else {
                    *(float2*)((float*)outv + (size_t)r1 * NC + cn) = make_float2(v2, v3);
                }
            }
        }
    }
}

// ------- LayerNorm(d=256) + GELU, warp per row (bf16 in/out, fp32 math) ----
__global__ void ln_gelu_kernel(const bf16* __restrict__ in, const float* __restrict__ g,
                               const float* __restrict__ be, bf16* __restrict__ out,
                               int M) {
    int row  = blockIdx.x * 8 + (threadIdx.x >> 5);
    int lane = threadIdx.x & 31;
    if (row >= M) return;
    uint4 q = *(const uint4*)(in + (size_t)row * 256 + lane * 8);
    const bf162* b2 = (const bf162*)&q;
    float v[8];
#pragma unroll
    for (int c = 0; c < 4; c++) {
        float2 f = __bfloat1622float2(b2[c]);
        v[2 * c] = f.x; v[2 * c + 1] = f.y;
    }
    float s = 0.f;
#pragma unroll
    for (int c = 0; c < 8; c++) s += v[c];
#pragma unroll
    for (int o = 16; o; o >>= 1) s += __shfl_xor_sync(0xffffffffu, s, o);
    float mean = s * (1.0f / 256.0f);
    float var = 0.f;
#pragma unroll
    for (int c = 0; c < 8; c++) { float d = v[c] - mean; var += d * d; }
#pragma unroll
    for (int o = 16; o; o >>= 1) var += __shfl_xor_sync(0xffffffffu, var, o);
    float rstd = rsqrtf(var * (1.0f / 256.0f) + 1e-5f);

    int c0 = lane * 8;
    float4 g0 = *(const float4*)(g + c0),  g1 = *(const float4*)(g + c0 + 4);
    float4 e0 = *(const float4*)(be + c0), e1 = *(const float4*)(be + c0 + 4);
    float gg[8] = {g0.x, g0.y, g0.z, g0.w, g1.x, g1.y, g1.z, g1.w};
    float ee[8] = {e0.x, e0.y, e0.z, e0.w, e1.x, e1.y, e1.z, e1.w};
    float o[8];
#pragma unroll
    for (int c = 0; c < 8; c++)
        o[c] = gelu_f((v[c] - mean) * rstd * gg[c] + ee[c]);
    uint4 w;
    bf162* wb = (bf162*)&w;
#pragma unroll
    for (int c = 0; c < 4; c++)
        wb[c] = __float22bfloat162_rn(make_float2(o[2 * c], o[2 * c + 1]));
    *(uint4*)(out + (size_t)row * 256 + lane * 8) = w;
}

// ---------------- log_softmax over 64 cols, warp per row, in-place ----------------
__global__ void lsm_kernel(float* __restrict__ io, int M) {
    int row  = blockIdx.x * 8 + (threadIdx.x >> 5);
    int lane = threadIdx.x & 31;
    if (row >= M) return;
    float* r = io + (size_t)row * 64;
    float2 v = *(float2*)(r + lane * 2);
    float m = fmaxf(v.x, v.y);
#pragma unroll
    for (int o = 16; o; o >>= 1) m = fmaxf(m, __shfl_xor_sync(0xffffffffu, m, o));
    float s = expf(v.x - m) + expf(v.y - m);
#pragma unroll
    for (int o = 16; o; o >>= 1) s += __shfl_xor_sync(0xffffffffu, s, o);
    float l = m + logf(s);
    v.x -= l; v.y -= l;
    *(float2*)(r + lane * 2) = v;
}

// ---------------- host orchestration ----------------
extern "C" void kernel_launch(void* const* d_in, const int* in_sizes, int n_in,
                              void* d_out, int out_size) {
    const float* x   = (const float*)d_in[0];
    const int*   ei  = (const int*)d_in[1];
    const int*   src = ei;
    const int*   dst = ei + EE;
    const float* Wc[3] = {(const float*)d_in[2],  (const float*)d_in[8],  (const float*)d_in[14]};
    const float* bc[3] = {(const float*)d_in[3],  (const float*)d_in[9],  (const float*)d_in[15]};
    const float* Wp[3] = {(const float*)d_in[4],  (const float*)d_in[10], (const float*)d_in[16]};
    const float* bp[3] = {(const float*)d_in[5],  (const float*)d_in[11], (const float*)d_in[17]};
    const float* gn[3] = {(const float*)d_in[6],  (const float*)d_in[12], (const float*)d_in[18]};
    const float* be[3] = {(const float*)d_in[7],  (const float*)d_in[13], (const float*)d_in[19]};
    const float* W_in = (const float*)d_in[20];
    const float* b_in = (const float*)d_in[21];
    const float* Wf1  = (const float*)d_in[22];
    const float* bf1  = (const float*)d_in[23];
    const float* Wf2  = (const float*)d_in[24];
    const float* bf2  = (const float*)d_in[25];
    float* outp = (float*)d_out;

    bf16 *p, *sA, *sB, *h, *u, *xb;
    unsigned* wpack;
    float *dv, *csrw;
    int *dg, *rowptr, *cur, *tmp, *bsum, *csrs;
    cudaGetSymbolAddress((void**)&p,  g_p);
    cudaGetSymbolAddress((void**)&sA, g_sA);
    cudaGetSymbolAddress((void**)&sB, g_sB);
    cudaGetSymbolAddress((void**)&h,  g_h);
    cudaGetSymbolAddress((void**)&u,  g_u);
    cudaGetSymbolAddress((void**)&xb, g_xb);
    cudaGetSymbolAddress((void**)&wpack, g_wpack);
    cudaGetSymbolAddress((void**)&dv, g_dinv);
    cudaGetSymbolAddress((void**)&dg, g_deg);
    cudaGetSymbolAddress((void**)&rowptr, g_rowptr);
    cudaGetSymbolAddress((void**)&cur, g_cur);
    cudaGetSymbolAddress((void**)&tmp, g_tmp);
    cudaGetSymbolAddress((void**)&bsum, g_bsum);
    cudaGetSymbolAddress((void**)&csrs, g_csrs);
    cudaGetSymbolAddress((void**)&csrw, g_csrw);

    // ---- pack weights (u32 [K/2][N]) + convert x -> bf16 ----
    unsigned* wc0p = wpack;           unsigned* wc1p = wpack + 16384;
    unsigned* wc2p = wpack + 49152;   unsigned* wp0p = wpack + 81920;
    unsigned* wp1p = wpack + 98304;   unsigned* wp2p = wpack + 131072;
    unsigned* winp = wpack + 163840;  unsigned* wf1p = wpack + 180224;
    unsigned* wf2p = wpack + 245760;
    PackArgs pa;
    pa.seg[0] = {Wc[0], wc0p, 256, 0, 16384};
    pa.seg[1] = {Wc[1], wc1p, 256, 0, 32768};
    pa.seg[2] = {Wc[2], wc2p, 256, 0, 32768};
    pa.seg[3] = {Wp[0], wp0p, 256, 0, 16384};
    pa.seg[4] = {Wp[1], wp1p, 256, 0, 32768};
    pa.seg[5] = {Wp[2], wp2p, 256, 0, 32768};
    pa.seg[6] = {W_in,  winp, 256, 0, 16384};
    pa.seg[7] = {Wf1,   wf1p, 512, 0, 65536};
    pa.seg[8] = {Wf2,   wf2p, 64,  0, 16384};
    pa.seg[9] = {x, (unsigned*)xb, 0, 1, (unsigned)(NN * 64)};
    pa.total = 16384 + 32768 + 32768 + 16384 + 32768 + 32768 + 16384 + 65536 + 16384
             + (unsigned)(NN * 64);
    pack_kernel<<<(pa.total + 255) / 256, 256>>>(pa);

    // ---- CSR build ----
    const int NB = (NN + 1023) / 1024;   // 49
    cudaMemsetAsync(dg, 0, NN * sizeof(int));
    deg_kernel<<<(EE + 255) / 256, 256>>>(dst, dg, EE);
    dinv_kernel<<<(NN + 255) / 256, 256>>>(dg, dv, NN);
    scan_blk<<<NB, 1024>>>(dg, tmp, bsum, NN);
    scan_top<<<1, 64>>>(bsum, NB);
    scan_add<<<(NN + 1 + 255) / 256, 256>>>(tmp, bsum, rowptr, cur, NN);
    fill_kernel<<<(EE + 255) / 256, 256>>>(src, dst, dv, cur, csrs, csrw, EE);

    const int SMEM128 = 2 * (128 * 20 + 16 * 136) * 4;   // 37888 B
    const int SMEM64  = 2 * (128 * 20 + 16 * 72)  * 4;   // 29696 B

    const dim3 gridN256(2, (NN + 127) / 128);
    const dim3 gridN512(4, (NN + 127) / 128);
    const dim3 gridN64 (1, (NN + 127) / 128);

    const unsigned* WcP[3] = {wc0p, wc1p, wc2p};
    const unsigned* WpP[3] = {wp0p, wp1p, wp2p};

    const bf16* hin  = xb;   int din   = 128;
    const bf16* skip = xb;   int dskip = 128;
    bf16* snew_arr[3] = {sA, sB, sA};

    for (int l = 0; l < 3; l++) {
        if (din == 128)
            gather_kernel<128><<<NN, 256>>>(hin, dv, rowptr, csrs, csrw, p);
        else
            gather_kernel<256><<<NN, 256>>>(hin, dv, rowptr, csrs, csrw, p);
        bf16* snew = snew_arr[l];
        bf16_gemm<128, 0, true, false, true><<<gridN256, 256, SMEM128>>>(
            p, WcP[l], din, skip, WpP[l], dskip,
            bc[l], bp[l], nullptr, snew, NN, 256);
        ln_gelu_kernel<<<(NN + 7) / 8, 256>>>(snew, gn[l], be[l], h, NN);
        hin = h; din = 256;
        skip = snew; dskip = 256;
    }

    // t = x @ W_in + b_in + h   (sB free after layer 2 consumed it as skip)
    bf16_gemm<128, 0, false, true, true><<<gridN256, 256, SMEM128>>>(
        xb, winp, 128, nullptr, nullptr, 0, b_in, nullptr, h, sB, NN, 256);
    // u = gelu(t @ Wf1 + bf1)
    bf16_gemm<128, 1, false, false, true><<<gridN512, 256, SMEM128>>>(
        sB, wf1p, 256, nullptr, nullptr, 0, bf1, nullptr, nullptr, u, NN, 512);
    // logits = u @ Wf2 + bf2  -> d_out (fp32)
    bf16_gemm<64, 0, false, false, false><<<gridN64, 256, SMEM64>>>(
        u, wf2p, 512, nullptr, nullptr, 0, bf2, nullptr, nullptr, outp, NN, 64);
    // in-place log_softmax
    lsm_kernel<<<(NN + 7) / 8, 256>>>(outp, NN);
}

// round 12
// speedup vs baseline: 4.1428x; 1.5088x over previous
#include <cuda_runtime.h>
#include <cuda_bf16.h>
#include <math.h>
#include <stdint.h>

#define NN 50000
#define EE 800000

typedef __nv_bfloat16 bf16;
typedef __nv_bfloat162 bf162;

// ---------------- device scratch (no allocation allowed) ----------------
__device__ __align__(256) bf16  g_p [NN * 256];
__device__ __align__(256) bf16  g_sA[NN * 256];
__device__ __align__(256) bf16  g_sB[NN * 256];
__device__ __align__(256) bf16  g_h [NN * 256];
__device__ __align__(256) bf16  g_u [NN * 512];
__device__ __align__(256) bf16  g_xb[NN * 128];
__device__ __align__(256) unsigned g_wpack[262144];
__device__ float g_dinv[NN];
__device__ int   g_deg[NN];
__device__ int   g_rowptr[NN + 1];
__device__ int   g_cur[NN];
__device__ int   g_tmp[NN];
__device__ int   g_bsum[64];
__device__ int   g_csrs[EE];
__device__ float g_csrw[EE];

__device__ __forceinline__ float gelu_f(float x) {
    return 0.5f * x * (1.0f + erff(x * 0.7071067811865476f));
}

// ---------------- weight pack / x convert ----------------
struct PackSeg { const float* src; unsigned* dst; int ncols; int mode; unsigned count; };
struct PackArgs { PackSeg seg[10]; unsigned total; };

__global__ void pack_kernel(PackArgs pa) {
    unsigned u = blockIdx.x * 256 + threadIdx.x;
    if (u >= pa.total) return;
    int s = 0; unsigned base = 0;
    while (u >= base + pa.seg[s].count) { base += pa.seg[s].count; s++; }
    unsigned i = u - base;
    const float* src = pa.seg[s].src;
    float lo, hi;
    if (pa.seg[s].mode == 0) {
        int N = pa.seg[s].ncols;
        unsigned kp = i / N, n = i % N;
        lo = src[(size_t)(2 * kp) * N + n];
        hi = src[(size_t)(2 * kp + 1) * N + n];
    } else {
        lo = src[2 * (size_t)i];
        hi = src[2 * (size_t)i + 1];
    }
    bf162 h2 = __float22bfloat162_rn(make_float2(lo, hi));
    pa.seg[s].dst[i] = *(unsigned*)&h2;
}

// ---------------- degree / dinv ----------------
__global__ void deg_kernel(const int* __restrict__ dst, int* __restrict__ deg, int E) {
    int e = blockIdx.x * blockDim.x + threadIdx.x;
    if (e < E) atomicAdd(&deg[dst[e]], 1);
}

__global__ void dinv_kernel(const int* __restrict__ deg, float* __restrict__ dinv, int n) {
    int i = blockIdx.x * blockDim.x + threadIdx.x;
    if (i < n) dinv[i] = rsqrtf((float)deg[i] + 1.0f);
}

// ---------------- 3-kernel exclusive scan of deg -> rowptr ----------------
__global__ void scan_blk(const int* __restrict__ deg, int* __restrict__ tmp,
                         int* __restrict__ bsum, int n) {
    __shared__ int s[1024];
    int i = blockIdx.x * 1024 + threadIdx.x;
    int v = (i < n) ? deg[i] : 0;
    s[threadIdx.x] = v;
    __syncthreads();
#pragma unroll
    for (int o = 1; o < 1024; o <<= 1) {
        int t = (threadIdx.x >= o) ? s[threadIdx.x - o] : 0;
        __syncthreads();
        s[threadIdx.x] += t;
        __syncthreads();
    }
    if (i < n) tmp[i] = s[threadIdx.x];
    if (threadIdx.x == 1023) bsum[blockIdx.x] = s[1023];
}

__global__ void scan_top(int* __restrict__ bsum, int nb) {
    __shared__ int s[64];
    int v = (threadIdx.x < nb) ? bsum[threadIdx.x] : 0;
    s[threadIdx.x] = v;
    __syncthreads();
#pragma unroll
    for (int o = 1; o < 64; o <<= 1) {
        int t = (threadIdx.x >= o) ? s[threadIdx.x - o] : 0;
        __syncthreads();
        s[threadIdx.x] += t;
        __syncthreads();
    }
    if (threadIdx.x < nb) bsum[threadIdx.x] = s[threadIdx.x];
}

__global__ void scan_add(const int* __restrict__ tmp, const int* __restrict__ bsum,
                         int* __restrict__ rowptr, int* __restrict__ cur, int n) {
    int i = blockIdx.x * blockDim.x + threadIdx.x;
    if (i > n) return;
    int v;
    if (i == 0) v = 0;
    else {
        int j = i - 1;
        v = tmp[j] + ((j >= 1024) ? bsum[j / 1024 - 1] : 0);
    }
    rowptr[i] = v;
    if (i < n) cur[i] = v;
}

// ---------------- CSR bucket fill (also computes edge weights) ----------------
__global__ void fill_kernel(const int* __restrict__ src, const int* __restrict__ dst,
                            const float* __restrict__ dinv, int* __restrict__ cur,
                            int* __restrict__ csrs, float* __restrict__ csrw, int E) {
    int e = blockIdx.x * blockDim.x + threadIdx.x;
    if (e >= E) return;
    int s = src[e], d = dst[e];
    int pos = atomicAdd(&cur[d], 1);
    csrs[pos] = s;
    csrw[pos] = dinv[s] * dinv[d];
}

// ------- CSR gather, warp per row (bf16 in/out, fp32 accumulate) ------------
// p[row] = dinv[row]^2*h[row] + sum_j w_j*h[src_j]
// D=256: lane holds 8 channels (uint4); D=128: lane holds 4 channels (uint2).
template<int D>
__global__ __launch_bounds__(256)
void gather_warp(const bf16* __restrict__ h, const float* __restrict__ dinv,
                 const int* __restrict__ rowptr, const int* __restrict__ csrs,
                 const float* __restrict__ csrw, bf16* __restrict__ p) {
    constexpr int VEC = D / 32;     // bf16 per lane
    constexpr int N2  = VEC / 2;    // bf162 per lane
    const int wid  = threadIdx.x >> 5;
    const int lane = threadIdx.x & 31;
    const int row  = blockIdx.x * 8 + wid;
    if (row >= NN) return;

    const int start = rowptr[row];
    const int end   = rowptr[row + 1];
    const bf16* selfp = h + (size_t)row * D + lane * VEC;

    float acc[VEC];
    {
        float w = dinv[row]; w = w * w;
        uint4 q;
        if (VEC == 8) q = *(const uint4*)selfp;
        else { uint2 t = *(const uint2*)selfp; q.x = t.x; q.y = t.y; q.z = 0; q.w = 0; }
        const bf162* b2 = (const bf162*)&q;
#pragma unroll
        for (int c = 0; c < N2; c++) {
            float2 f = __bfloat1622float2(b2[c]);
            acc[2 * c]     = w * f.x;
            acc[2 * c + 1] = w * f.y;
        }
    }

    int j = start;
    for (; j + 1 < end; j += 2) {
        int   s0 = csrs[j],     s1 = csrs[j + 1];
        float w0 = csrw[j],     w1 = csrw[j + 1];
        const bf16* p0 = h + (size_t)s0 * D + lane * VEC;
        const bf16* p1 = h + (size_t)s1 * D + lane * VEC;
        uint4 q0, q1;
        if (VEC == 8) { q0 = *(const uint4*)p0; q1 = *(const uint4*)p1; }
        else {
            uint2 t0 = *(const uint2*)p0, t1 = *(const uint2*)p1;
            q0.x = t0.x; q0.y = t0.y; q1.x = t1.x; q1.y = t1.y;
            q0.z = q0.w = q1.z = q1.w = 0;
        }
        const bf162* a0 = (const bf162*)&q0;
        const bf162* a1 = (const bf162*)&q1;
#pragma unroll
        for (int c = 0; c < N2; c++) {
            float2 f0 = __bfloat1622float2(a0[c]);
            float2 f1 = __bfloat1622float2(a1[c]);
            acc[2 * c]     += w0 * f0.x + w1 * f1.x;
            acc[2 * c + 1] += w0 * f0.y + w1 * f1.y;
        }
    }
    if (j < end) {
        int   s0 = csrs[j];
        float w0 = csrw[j];
        const bf16* p0 = h + (size_t)s0 * D + lane * VEC;
        uint4 q0;
        if (VEC == 8) q0 = *(const uint4*)p0;
        else { uint2 t0 = *(const uint2*)p0; q0.x = t0.x; q0.y = t0.y; q0.z = q0.w = 0; }
        const bf162* a0 = (const bf162*)&q0;
#pragma unroll
        for (int c = 0; c < N2; c++) {
            float2 f0 = __bfloat1622float2(a0[c]);
            acc[2 * c]     += w0 * f0.x;
            acc[2 * c + 1] += w0 * f0.y;
        }
    }

    bf16* prow = p + (size_t)row * D + lane * VEC;
    uint4 o;
    bf162* ob = (bf162*)&o;
#pragma unroll
    for (int c = 0; c < N2; c++)
        ob[c] = __float22bfloat162_rn(make_float2(acc[2 * c], acc[2 * c + 1]));
    if (VEC == 8) *(uint4*)prow = o;
    else          *(uint2*)prow = make_uint2(o.x, o.y);
}

// ---------------- bf16 tensor-core GEMM (m16n8k16) ----------------
// out = act( A1@W1 [+ A2@W2] + b1 [+ b2] [+ addM] ). K % 32 == 0.
// A: bf16 row-major [M][K]. W: packed u32 [K/2][NC] (k-pairs).
// BM=128, BN in {128,64}, BK=32 (halves), 256 threads, warp tile 32 x BN/2.
template<int BN, int ACT, bool DUAL, bool ADDM, bool OUTBF>
__global__ __launch_bounds__(256)
void bf16_gemm(const bf16* __restrict__ A1, const unsigned* __restrict__ W1, int K1,
               const bf16* __restrict__ A2, const unsigned* __restrict__ W2, int K2,
               const float* __restrict__ b1, const float* __restrict__ b2,
               const bf16* __restrict__ addM, void* __restrict__ outv,
               int M, int NC) {
    constexpr int BM = 128;
    constexpr int ASTR = 20;                // A smem row stride (u32): 20g+t distinct mod 32
    constexpr int BSTR = BN + 8;            // B smem row stride (u32): ≡8 mod 32
    constexpr int AU  = BM * ASTR;          // u32 per A buffer
    constexpr int BU  = 16 * BSTR;          // 16 kp-rows
    constexpr int BUFF = AU + BU;
    constexpr int NT  = BN / 16;            // n-tiles per warp (8 cols each)

    extern __shared__ __align__(16) unsigned smem[];

    const int tid  = threadIdx.x;
    const int lane = tid & 31;
    const int warp = tid >> 5;
    const int wm   = warp & 3;
    const int wn   = warp >> 2;
    const int gid  = lane >> 2;
    const int tig  = lane & 3;
    const int rowBase = blockIdx.y * BM;
    const int colBase = blockIdx.x * BN;

    const uint32_t sbase = (uint32_t)__cvta_generic_to_shared(smem);

    float acc[2][NT][4];
#pragma unroll
    for (int mt = 0; mt < 2; mt++)
#pragma unroll
        for (int nt = 0; nt < NT; nt++)
#pragma unroll
            for (int i = 0; i < 4; i++) acc[mt][nt][i] = 0.0f;

    const int nPhase = DUAL ? 2 : 1;
    for (int phase = 0; phase < nPhase; ++phase) {
        const bf16* A     = (phase == 0) ? A1 : A2;
        const unsigned* W = (phase == 0) ? W1 : W2;
        const int K       = (phase == 0) ? K1 : K2;
        const int nTiles  = K / 32;

        auto cpTile = [&](int t, int b) {
            const int k0 = t * 32;          // in bf16 elements
            const uint32_t aoff = sbase + (uint32_t)(b * BUFF) * 4u;
            const uint32_t boff = aoff + (uint32_t)AU * 4u;
            // A: 128 rows x 16 u32 = 512 16B-chunks
#pragma unroll
            for (int i = 0; i < 2; i++) {
                int idx = tid + i * 256;
                int r   = idx >> 2;
                int c4  = (idx & 3) << 2;       // u32 offset within row
                int grow = rowBase + r;
                int sz = (grow < M) ? 16 : 0;
                const bf16* g = A + (size_t)((grow < M) ? grow : 0) * K + k0 + 2 * c4;
                uint32_t sa = aoff + (uint32_t)(r * ASTR + c4) * 4u;
                asm volatile("cp.async.ca.shared.global [%0], [%1], 16, %2;\n"
                             :: "r"(sa), "l"(g), "r"(sz));
            }
            // B: 16 kp-rows x BN u32
            constexpr int BI = (BN == 128) ? 2 : 1;
#pragma unroll
            for (int i = 0; i < BI; i++) {
                int idx = tid + i * 256;
                int r   = idx >> ((BN == 128) ? 5 : 4);
                int c4  = (idx & ((BN / 4) - 1)) << 2;
                const unsigned* g = W + (size_t)(k0 / 2 + r) * NC + colBase + c4;
                uint32_t sa = boff + (uint32_t)(r * BSTR + c4) * 4u;
                asm volatile("cp.async.ca.shared.global [%0], [%1], 16, %2;\n"
                             :: "r"(sa), "l"(g), "r"(16));
            }
            asm volatile("cp.async.commit_group;\n" ::);
        };

        int buf = 0;
        cpTile(0, 0);
        for (int t = 0; t < nTiles; t++) {
            const bool hasNext = (t + 1) < nTiles;
            if (hasNext) {
                cpTile(t + 1, buf ^ 1);
                asm volatile("cp.async.wait_group 1;\n" ::);
            } else {
                asm volatile("cp.async.wait_group 0;\n" ::);
            }
            __syncthreads();

            const unsigned* As = smem + buf * BUFF;
            const unsigned* Bs = As + AU;
#pragma unroll
            for (int ks = 0; ks < 2; ks++) {
                const int kb = ks * 8;          // u32 col base (A) / kp row base (B)
                unsigned a[2][4];
                unsigned b[NT][2];
#pragma unroll
                for (int mt = 0; mt < 2; mt++) {
                    int m = wm * 32 + mt * 16 + gid;
                    a[mt][0] = As[m * ASTR + kb + tig];
                    a[mt][1] = As[(m + 8) * ASTR + kb + tig];
                    a[mt][2] = As[m * ASTR + kb + tig + 4];
                    a[mt][3] = As[(m + 8) * ASTR + kb + tig + 4];
                }
#pragma unroll
                for (int nt = 0; nt < NT; nt++) {
                    int n = wn * (BN / 2) + nt * 8 + gid;
                    b[nt][0] = Bs[(kb + tig) * BSTR + n];
                    b[nt][1] = Bs[(kb + tig + 4) * BSTR + n];
                }
#pragma unroll
                for (int mt = 0; mt < 2; mt++)
#pragma unroll
                    for (int nt = 0; nt < NT; nt++) {
                        asm volatile(
                            "mma.sync.aligned.m16n8k16.row.col.f32.bf16.bf16.f32 "
                            "{%0,%1,%2,%3}, {%4,%5,%6,%7}, {%8,%9}, {%0,%1,%2,%3};\n"
                            : "+f"(acc[mt][nt][0]), "+f"(acc[mt][nt][1]),
                              "+f"(acc[mt][nt][2]), "+f"(acc[mt][nt][3])
                            : "r"(a[mt][0]), "r"(a[mt][1]), "r"(a[mt][2]), "r"(a[mt][3]),
                              "r"(b[nt][0]), "r"(b[nt][1]));
                    }
            }
            __syncthreads();
            buf ^= 1;
        }
    }

    // ---------------- epilogue ----------------
#pragma unroll
    for (int mt = 0; mt < 2; mt++) {
        const int r0 = rowBase + wm * 32 + mt * 16 + gid;
        const int r1 = r0 + 8;
#pragma unroll
        for (int nt = 0; nt < NT; nt++) {
            const int cn = colBase + wn * (BN / 2) + nt * 8 + tig * 2;
            float bias0 = b1[cn], bias1 = b1[cn + 1];
            if (DUAL) { bias0 += b2[cn]; bias1 += b2[cn + 1]; }
            float v0 = acc[mt][nt][0] + bias0;
            float v1 = acc[mt][nt][1] + bias1;
            float v2 = acc[mt][nt][2] + bias0;
            float v3 = acc[mt][nt][3] + bias1;
            if (r0 < M) {
                if (ADDM) {
                    unsigned q = *(const unsigned*)(addM + (size_t)r0 * NC + cn);
                    float2 f = __bfloat1622float2(*(const bf162*)&q);
                    v0 += f.x; v1 += f.y;
                }
                if (ACT == 1) { v0 = gelu_f(v0); v1 = gelu_f(v1); }
                if (OUTBF) {
                    bf162 o = __float22bfloat162_rn(make_float2(v0, v1));
                    *(unsigned*)((bf16*)outv + (size_t)r0 * NC + cn) = *(unsigned*)&o;
                } else {
                    *(float2*)((float*)outv + (size_t)r0 * NC + cn) = make_float2(v0, v1);
                }
            }
            if (r1 < M) {
                if (ADDM) {
                    unsigned q = *(const unsigned*)(addM + (size_t)r1 * NC + cn);
                    float2 f = __bfloat1622float2(*(const bf162*)&q);
                    v2 += f.x; v3 += f.y;
                }
                if (ACT == 1) { v2 = gelu_f(v2); v3 = gelu_f(v3); }
                if (OUTBF) {
                    bf162 o = __float22bfloat162_rn(make_float2(v2, v3));
                    *(unsigned*)((bf16*)outv + (size_t)r1 * NC + cn) = *(unsigned*)&o;
                } else {
                    *(float2*)((float*)outv + (size_t)r1 * NC + cn) = make_float2(v2, v3);
                }
            }
        }
    }
}

// ------- LayerNorm(d=256) + GELU, warp per row (bf16 in/out, fp32 math) ----
__global__ void ln_gelu_kernel(const bf16* __restrict__ in, const float* __restrict__ g,
                               const float* __restrict__ be, bf16* __restrict__ out,
                               int M) {
    int row  = blockIdx.x * 8 + (threadIdx.x >> 5);
    int lane = threadIdx.x & 31;
    if (row >= M) return;
    uint4 q = *(const uint4*)(in + (size_t)row * 256 + lane * 8);
    const bf162* b2 = (const bf162*)&q;
    float v[8];
#pragma unroll
    for (int c = 0; c < 4; c++) {
        float2 f = __bfloat1622float2(b2[c]);
        v[2 * c] = f.x; v[2 * c + 1] = f.y;
    }
    float s = 0.f;
#pragma unroll
    for (int c = 0; c < 8; c++) s += v[c];
#pragma unroll
    for (int o = 16; o; o >>= 1) s += __shfl_xor_sync(0xffffffffu, s, o);
    float mean = s * (1.0f / 256.0f);
    float var = 0.f;
#pragma unroll
    for (int c = 0; c < 8; c++) { float d = v[c] - mean; var += d * d; }
#pragma unroll
    for (int o = 16; o; o >>= 1) var += __shfl_xor_sync(0xffffffffu, var, o);
    float rstd = rsqrtf(var * (1.0f / 256.0f) + 1e-5f);

    int c0 = lane * 8;
    float4 g0 = *(const float4*)(g + c0),  g1 = *(const float4*)(g + c0 + 4);
    float4 e0 = *(const float4*)(be + c0), e1 = *(const float4*)(be + c0 + 4);
    float gg[8] = {g0.x, g0.y, g0.z, g0.w, g1.x, g1.y, g1.z, g1.w};
    float ee[8] = {e0.x, e0.y, e0.z, e0.w, e1.x, e1.y, e1.z, e1.w};
    float o[8];
#pragma unroll
    for (int c = 0; c < 8; c++)
        o[c] = gelu_f((v[c] - mean) * rstd * gg[c] + ee[c]);
    uint4 w;
    bf162* wb = (bf162*)&w;
#pragma unroll
    for (int c = 0; c < 4; c++)
        wb[c] = __float22bfloat162_rn(make_float2(o[2 * c], o[2 * c + 1]));
    *(uint4*)(out + (size_t)row * 256 + lane * 8) = w;
}

// ---------------- log_softmax over 64 cols, warp per row, in-place ----------------
__global__ void lsm_kernel(float* __restrict__ io, int M) {
    int row  = blockIdx.x * 8 + (threadIdx.x >> 5);
    int lane = threadIdx.x & 31;
    if (row >= M) return;
    float* r = io + (size_t)row * 64;
    float2 v = *(float2*)(r + lane * 2);
    float m = fmaxf(v.x, v.y);
#pragma unroll
    for (int o = 16; o; o >>= 1) m = fmaxf(m, __shfl_xor_sync(0xffffffffu, m, o));
    float s = expf(v.x - m) + expf(v.y - m);
#pragma unroll
    for (int o = 16; o; o >>= 1) s += __shfl_xor_sync(0xffffffffu, s, o);
    float l = m + logf(s);
    v.x -= l; v.y -= l;
    *(float2*)(r + lane * 2) = v;
}

// ---------------- host orchestration ----------------
extern "C" void kernel_launch(void* const* d_in, const int* in_sizes, int n_in,
                              void* d_out, int out_size) {
    const float* x   = (const float*)d_in[0];
    const int*   ei  = (const int*)d_in[1];
    const int*   src = ei;
    const int*   dst = ei + EE;
    const float* Wc[3] = {(const float*)d_in[2],  (const float*)d_in[8],  (const float*)d_in[14]};
    const float* bc[3] = {(const float*)d_in[3],  (const float*)d_in[9],  (const float*)d_in[15]};
    const float* Wp[3] = {(const float*)d_in[4],  (const float*)d_in[10], (const float*)d_in[16]};
    const float* bp[3] = {(const float*)d_in[5],  (const float*)d_in[11], (const float*)d_in[17]};
    const float* gn[3] = {(const float*)d_in[6],  (const float*)d_in[12], (const float*)d_in[18]};
    const float* be[3] = {(const float*)d_in[7],  (const float*)d_in[13], (const float*)d_in[19]};
    const float* W_in = (const float*)d_in[20];
    const float* b_in = (const float*)d_in[21];
    const float* Wf1  = (const float*)d_in[22];
    const float* bf1  = (const float*)d_in[23];
    const float* Wf2  = (const float*)d_in[24];
    const float* bf2  = (const float*)d_in[25];
    float* outp = (float*)d_out;

    bf16 *p, *sA, *sB, *h, *u, *xb;
    unsigned* wpack;
    float *dv, *csrw;
    int *dg, *rowptr, *cur, *tmp, *bsum, *csrs;
    cudaGetSymbolAddress((void**)&p,  g_p);
    cudaGetSymbolAddress((void**)&sA, g_sA);
    cudaGetSymbolAddress((void**)&sB, g_sB);
    cudaGetSymbolAddress((void**)&h,  g_h);
    cudaGetSymbolAddress((void**)&u,  g_u);
    cudaGetSymbolAddress((void**)&xb, g_xb);
    cudaGetSymbolAddress((void**)&wpack, g_wpack);
    cudaGetSymbolAddress((void**)&dv, g_dinv);
    cudaGetSymbolAddress((void**)&dg, g_deg);
    cudaGetSymbolAddress((void**)&rowptr, g_rowptr);
    cudaGetSymbolAddress((void**)&cur, g_cur);
    cudaGetSymbolAddress((void**)&tmp, g_tmp);
    cudaGetSymbolAddress((void**)&bsum, g_bsum);
    cudaGetSymbolAddress((void**)&csrs, g_csrs);
    cudaGetSymbolAddress((void**)&csrw, g_csrw);

    // ---- pack weights (u32 [K/2][N]) + convert x -> bf16 ----
    unsigned* wc0p = wpack;           unsigned* wc1p = wpack + 16384;
    unsigned* wc2p = wpack + 49152;   unsigned* wp0p = wpack + 81920;
    unsigned* wp1p = wpack + 98304;   unsigned* wp2p = wpack + 131072;
    unsigned* winp = wpack + 163840;  unsigned* wf1p = wpack + 180224;
    unsigned* wf2p = wpack + 245760;
    PackArgs pa;
    pa.seg[0] = {Wc[0], wc0p, 256, 0, 16384};
    pa.seg[1] = {Wc[1], wc1p, 256, 0, 32768};
    pa.seg[2] = {Wc[2], wc2p, 256, 0, 32768};
    pa.seg[3] = {Wp[0], wp0p, 256, 0, 16384};
    pa.seg[4] = {Wp[1], wp1p, 256, 0, 32768};
    pa.seg[5] = {Wp[2], wp2p, 256, 0, 32768};
    pa.seg[6] = {W_in,  winp, 256, 0, 16384};
    pa.seg[7] = {Wf1,   wf1p, 512, 0, 65536};
    pa.seg[8] = {Wf2,   wf2p, 64,  0, 16384};
    pa.seg[9] = {x, (unsigned*)xb, 0, 1, (unsigned)(NN * 64)};
    pa.total = 16384 + 32768 + 32768 + 16384 + 32768 + 32768 + 16384 + 65536 + 16384
             + (unsigned)(NN * 64);
    pack_kernel<<<(pa.total + 255) / 256, 256>>>(pa);

    // ---- CSR build ----
    const int NB = (NN + 1023) / 1024;   // 49
    cudaMemsetAsync(dg, 0, NN * sizeof(int));
    deg_kernel<<<(EE + 255) / 256, 256>>>(dst, dg, EE);
    dinv_kernel<<<(NN + 255) / 256, 256>>>(dg, dv, NN);
    scan_blk<<<NB, 1024>>>(dg, tmp, bsum, NN);
    scan_top<<<1, 64>>>(bsum, NB);
    scan_add<<<(NN + 1 + 255) / 256, 256>>>(tmp, bsum, rowptr, cur, NN);
    fill_kernel<<<(EE + 255) / 256, 256>>>(src, dst, dv, cur, csrs, csrw, EE);

    const int SMEM128 = 2 * (128 * 20 + 16 * 136) * 4;   // 37888 B
    const int SMEM64  = 2 * (128 * 20 + 16 * 72)  * 4;   // 29696 B

    const dim3 gridN256(2, (NN + 127) / 128);
    const dim3 gridN512(4, (NN + 127) / 128);
    const dim3 gridN64 (1, (NN + 127) / 128);
    const int gGather = (NN + 7) / 8;    // 6250 blocks, warp per row

    const unsigned* WcP[3] = {wc0p, wc1p, wc2p};
    const unsigned* WpP[3] = {wp0p, wp1p, wp2p};

    const bf16* hin  = xb;   int din   = 128;
    const bf16* skip = xb;   int dskip = 128;
    bf16* snew_arr[3] = {sA, sB, sA};

    for (int l = 0; l < 3; l++) {
        if (din == 128)
            gather_warp<128><<<gGather, 256>>>(hin, dv, rowptr, csrs, csrw, p);
        else
            gather_warp<256><<<gGather, 256>>>(hin, dv, rowptr, csrs, csrw, p);
        bf16* snew = snew_arr[l];
        bf16_gemm<128, 0, true, false, true><<<gridN256, 256, SMEM128>>>(
            p, WcP[l], din, skip, WpP[l], dskip,
            bc[l], bp[l], nullptr, snew, NN, 256);
        ln_gelu_kernel<<<(NN + 7) / 8, 256>>>(snew, gn[l], be[l], h, NN);
        hin = h; din = 256;
        skip = snew; dskip = 256;
    }

    // t = x @ W_in + b_in + h   (sB free after layer 2 consumed it as skip)
    bf16_gemm<128, 0, false, true, true><<<gridN256, 256, SMEM128>>>(
        xb, winp, 128, nullptr, nullptr, 0, b_in, nullptr, h, sB, NN, 256);
    // u = gelu(t @ Wf1 + bf1)
    bf16_gemm<128, 1, false, false, true><<<gridN512, 256, SMEM128>>>(
        sB, wf1p, 256, nullptr, nullptr, 0, bf1, nullptr, nullptr, u, NN, 512);
    // logits = u @ Wf2 + bf2  -> d_out (fp32)
    bf16_gemm<64, 0, false, false, false><<<gridN64, 256, SMEM64>>>(
        u, wf2p, 512, nullptr, nullptr, 0, bf2, nullptr, nullptr, outp, NN, 64);
    // in-place log_softmax
    lsm_kernel<<<(NN + 7) / 8, 256>>>(outp, NN);
}

// round 13
// speedup vs baseline: 4.2139x; 1.0172x over previous
#include <cuda_runtime.h>
#include <cuda_bf16.h>
#include <math.h>
#include <stdint.h>

#define NN 50000
#define EE 800000

typedef __nv_bfloat16 bf16;
typedef __nv_bfloat162 bf162;

// ---------------- device scratch (no allocation allowed) ----------------
__device__ __align__(256) bf16  g_p [NN * 256];
__device__ __align__(256) bf16  g_sA[NN * 256];
__device__ __align__(256) bf16  g_sB[NN * 256];
__device__ __align__(256) bf16  g_h [NN * 256];
__device__ __align__(256) bf16  g_u [NN * 512];
__device__ __align__(256) bf16  g_xb[NN * 128];
__device__ __align__(256) unsigned g_wpack[262144];
__device__ float g_dinv[NN];
__device__ int   g_deg[NN];
__device__ int   g_rowptr[NN + 1];
__device__ int   g_cur[NN];
__device__ int   g_tmp[NN];
__device__ int   g_bsum[64];
__device__ int   g_csrs[EE];
__device__ float g_csrw[EE];

__device__ __forceinline__ float gelu_f(float x) {
    return 0.5f * x * (1.0f + erff(x * 0.7071067811865476f));
}

// ---------------- weight pack / x convert ----------------
struct PackSeg { const float* src; unsigned* dst; int ncols; int mode; unsigned count; };
struct PackArgs { PackSeg seg[10]; unsigned total; };

__global__ void pack_kernel(PackArgs pa) {
    unsigned u = blockIdx.x * 256 + threadIdx.x;
    if (u >= pa.total) return;
    int s = 0; unsigned base = 0;
    while (u >= base + pa.seg[s].count) { base += pa.seg[s].count; s++; }
    unsigned i = u - base;
    const float* src = pa.seg[s].src;
    float lo, hi;
    if (pa.seg[s].mode == 0) {
        int N = pa.seg[s].ncols;
        unsigned kp = i / N, n = i % N;
        lo = src[(size_t)(2 * kp) * N + n];
        hi = src[(size_t)(2 * kp + 1) * N + n];
    } else {
        lo = src[2 * (size_t)i];
        hi = src[2 * (size_t)i + 1];
    }
    bf162 h2 = __float22bfloat162_rn(make_float2(lo, hi));
    pa.seg[s].dst[i] = *(unsigned*)&h2;
}

// ---------------- degree / dinv ----------------
__global__ void deg_kernel(const int* __restrict__ dst, int* __restrict__ deg, int E) {
    int e = blockIdx.x * blockDim.x + threadIdx.x;
    if (e < E) atomicAdd(&deg[dst[e]], 1);
}

__global__ void dinv_kernel(const int* __restrict__ deg, float* __restrict__ dinv, int n) {
    int i = blockIdx.x * blockDim.x + threadIdx.x;
    if (i < n) dinv[i] = rsqrtf((float)deg[i] + 1.0f);
}

// ---------------- 3-kernel exclusive scan of deg -> rowptr ----------------
__global__ void scan_blk(const int* __restrict__ deg, int* __restrict__ tmp,
                         int* __restrict__ bsum, int n) {
    __shared__ int s[1024];
    int i = blockIdx.x * 1024 + threadIdx.x;
    int v = (i < n) ? deg[i] : 0;
    s[threadIdx.x] = v;
    __syncthreads();
#pragma unroll
    for (int o = 1; o < 1024; o <<= 1) {
        int t = (threadIdx.x >= o) ? s[threadIdx.x - o] : 0;
        __syncthreads();
        s[threadIdx.x] += t;
        __syncthreads();
    }
    if (i < n) tmp[i] = s[threadIdx.x];
    if (threadIdx.x == 1023) bsum[blockIdx.x] = s[1023];
}

__global__ void scan_top(int* __restrict__ bsum, int nb) {
    __shared__ int s[64];
    int v = (threadIdx.x < nb) ? bsum[threadIdx.x] : 0;
    s[threadIdx.x] = v;
    __syncthreads();
#pragma unroll
    for (int o = 1; o < 64; o <<= 1) {
        int t = (threadIdx.x >= o) ? s[threadIdx.x - o] : 0;
        __syncthreads();
        s[threadIdx.x] += t;
        __syncthreads();
    }
    if (threadIdx.x < nb) bsum[threadIdx.x] = s[threadIdx.x];
}

__global__ void scan_add(const int* __restrict__ tmp, const int* __restrict__ bsum,
                         int* __restrict__ rowptr, int* __restrict__ cur, int n) {
    int i = blockIdx.x * blockDim.x + threadIdx.x;
    if (i > n) return;
    int v;
    if (i == 0) v = 0;
    else {
        int j = i - 1;
        v = tmp[j] + ((j >= 1024) ? bsum[j / 1024 - 1] : 0);
    }
    rowptr[i] = v;
    if (i < n) cur[i] = v;
}

// ---------------- CSR bucket fill (also computes edge weights) ----------------
__global__ void fill_kernel(const int* __restrict__ src, const int* __restrict__ dst,
                            const float* __restrict__ dinv, int* __restrict__ cur,
                            int* __restrict__ csrs, float* __restrict__ csrw, int E) {
    int e = blockIdx.x * blockDim.x + threadIdx.x;
    if (e >= E) return;
    int s = src[e], d = dst[e];
    int pos = atomicAdd(&cur[d], 1);
    csrs[pos] = s;
    csrw[pos] = dinv[s] * dinv[d];
}

// ------- CSR gather, warp per row (bf16 in/out, fp32 accumulate) ------------
template<int D>
__global__ __launch_bounds__(256)
void gather_warp(const bf16* __restrict__ h, const float* __restrict__ dinv,
                 const int* __restrict__ rowptr, const int* __restrict__ csrs,
                 const float* __restrict__ csrw, bf16* __restrict__ p) {
    constexpr int VEC = D / 32;     // bf16 per lane
    constexpr int N2  = VEC / 2;    // bf162 per lane
    const int wid  = threadIdx.x >> 5;
    const int lane = threadIdx.x & 31;
    const int row  = blockIdx.x * 8 + wid;
    if (row >= NN) return;

    const int start = rowptr[row];
    const int end   = rowptr[row + 1];
    const bf16* selfp = h + (size_t)row * D + lane * VEC;

    float acc[VEC];
    {
        float w = dinv[row]; w = w * w;
        uint4 q;
        if (VEC == 8) q = *(const uint4*)selfp;
        else { uint2 t = *(const uint2*)selfp; q.x = t.x; q.y = t.y; q.z = 0; q.w = 0; }
        const bf162* b2 = (const bf162*)&q;
#pragma unroll
        for (int c = 0; c < N2; c++) {
            float2 f = __bfloat1622float2(b2[c]);
            acc[2 * c]     = w * f.x;
            acc[2 * c + 1] = w * f.y;
        }
    }

    int j = start;
    for (; j + 1 < end; j += 2) {
        int   s0 = csrs[j],     s1 = csrs[j + 1];
        float w0 = csrw[j],     w1 = csrw[j + 1];
        const bf16* p0 = h + (size_t)s0 * D + lane * VEC;
        const bf16* p1 = h + (size_t)s1 * D + lane * VEC;
        uint4 q0, q1;
        if (VEC == 8) { q0 = *(const uint4*)p0; q1 = *(const uint4*)p1; }
        else {
            uint2 t0 = *(const uint2*)p0, t1 = *(const uint2*)p1;
            q0.x = t0.x; q0.y = t0.y; q1.x = t1.x; q1.y = t1.y;
            q0.z = q0.w = q1.z = q1.w = 0;
        }
        const bf162* a0 = (const bf162*)&q0;
        const bf162* a1 = (const bf162*)&q1;
#pragma unroll
        for (int c = 0; c < N2; c++) {
            float2 f0 = __bfloat1622float2(a0[c]);
            float2 f1 = __bfloat1622float2(a1[c]);
            acc[2 * c]     += w0 * f0.x + w1 * f1.x;
            acc[2 * c + 1] += w0 * f0.y + w1 * f1.y;
        }
    }
    if (j < end) {
        int   s0 = csrs[j];
        float w0 = csrw[j];
        const bf16* p0 = h + (size_t)s0 * D + lane * VEC;
        uint4 q0;
        if (VEC == 8) q0 = *(const uint4*)p0;
        else { uint2 t0 = *(const uint2*)p0; q0.x = t0.x; q0.y = t0.y; q0.z = q0.w = 0; }
        const bf162* a0 = (const bf162*)&q0;
#pragma unroll
        for (int c = 0; c < N2; c++) {
            float2 f0 = __bfloat1622float2(a0[c]);
            acc[2 * c]     += w0 * f0.x;
            acc[2 * c + 1] += w0 * f0.y;
        }
    }

    bf16* prow = p + (size_t)row * D + lane * VEC;
    uint4 o;
    bf162* ob = (bf162*)&o;
#pragma unroll
    for (int c = 0; c < N2; c++)
        ob[c] = __float22bfloat162_rn(make_float2(acc[2 * c], acc[2 * c + 1]));
    if (VEC == 8) *(uint4*)prow = o;
    else          *(uint2*)prow = make_uint2(o.x, o.y);
}

// ---------------- bf16 tensor-core GEMM (m16n8k16) ----------------
// out = act( A1@W1 [+ A2@W2] + b1 [+ b2] [+ addM] ). K % 32 == 0.
// A: bf16 row-major [M][K]. W: packed u32 [K/2][NC] (k-pairs).
// BM=128, BN in {128,64}, BK=32 (halves), 256 threads, warp tile 32 x BN/2.
// 3-stage cp.async pipeline, ONE __syncthreads per tile, 2 CTAs/SM.
template<int BN, int ACT, bool DUAL, bool ADDM, bool OUTBF>
__global__ __launch_bounds__(256, 2)
void bf16_gemm(const bf16* __restrict__ A1, const unsigned* __restrict__ W1, int K1,
               const bf16* __restrict__ A2, const unsigned* __restrict__ W2, int K2,
               const float* __restrict__ b1, const float* __restrict__ b2,
               const bf16* __restrict__ addM, void* __restrict__ outv,
               int M, int NC) {
    constexpr int BM = 128;
    constexpr int ASTR = 20;                // A smem row stride (u32): 20g+t distinct mod 32
    constexpr int BSTR = BN + 8;            // B smem row stride (u32): ≡8 mod 32
    constexpr int AU  = BM * ASTR;          // u32 per A buffer
    constexpr int BU  = 16 * BSTR;          // 16 kp-rows
    constexpr int BUFF = AU + BU;
    constexpr int NT  = BN / 16;            // n-tiles per warp (8 cols each)

    extern __shared__ __align__(16) unsigned smem[];

    const int tid  = threadIdx.x;
    const int lane = tid & 31;
    const int warp = tid >> 5;
    const int wm   = warp & 3;
    const int wn   = warp >> 2;
    const int gid  = lane >> 2;
    const int tig  = lane & 3;
    const int rowBase = blockIdx.y * BM;
    const int colBase = blockIdx.x * BN;

    const uint32_t sbase = (uint32_t)__cvta_generic_to_shared(smem);

    float acc[2][NT][4];
#pragma unroll
    for (int mt = 0; mt < 2; mt++)
#pragma unroll
        for (int nt = 0; nt < NT; nt++)
#pragma unroll
            for (int i = 0; i < 4; i++) acc[mt][nt][i] = 0.0f;

    const int nT1 = K1 / 32;
    const int nT  = nT1 + (DUAL ? (K2 / 32) : 0);

    // flat tile copy: global tile index t -> pipeline stage stg (0..2)
    auto cpTile = [&](int t, int stg) {
        const bf16* A; const unsigned* W; int K, k0;
        if (!DUAL || t < nT1) { A = A1; W = W1; K = K1; k0 = t * 32; }
        else                  { A = A2; W = W2; K = K2; k0 = (t - nT1) * 32; }
        const uint32_t aoff = sbase + (uint32_t)(stg * BUFF) * 4u;
        const uint32_t boff = aoff + (uint32_t)AU * 4u;
        // A: 128 rows x 16 u32 = 512 16B-chunks
#pragma unroll
        for (int i = 0; i < 2; i++) {
            int idx = tid + i * 256;
            int r   = idx >> 2;
            int c4  = (idx & 3) << 2;       // u32 offset within row
            int grow = rowBase + r;
            int sz = (grow < M) ? 16 : 0;
            const bf16* g = A + (size_t)((grow < M) ? grow : 0) * K + k0 + 2 * c4;
            uint32_t sa = aoff + (uint32_t)(r * ASTR + c4) * 4u;
            asm volatile("cp.async.ca.shared.global [%0], [%1], 16, %2;\n"
                         :: "r"(sa), "l"(g), "r"(sz));
        }
        // B: 16 kp-rows x BN u32
        constexpr int BI = (BN == 128) ? 2 : 1;
#pragma unroll
        for (int i = 0; i < BI; i++) {
            int idx = tid + i * 256;
            int r   = idx >> ((BN == 128) ? 5 : 4);
            int c4  = (idx & ((BN / 4) - 1)) << 2;
            const unsigned* g = W + (size_t)(k0 / 2 + r) * NC + colBase + c4;
            uint32_t sa = boff + (uint32_t)(r * BSTR + c4) * 4u;
            asm volatile("cp.async.ca.shared.global [%0], [%1], 16, %2;\n"
                         :: "r"(sa), "l"(g), "r"(16));
        }
        asm volatile("cp.async.commit_group;\n" ::);
    };

    // prologue: stages 0 and 1 in flight
    cpTile(0, 0);
    if (nT > 1) cpTile(1, 1);

    int stg = 0;
    for (int t = 0; t < nT; t++) {
        if (t + 1 < nT) {
            asm volatile("cp.async.wait_group 1;\n" ::);   // tile t complete
        } else {
            asm volatile("cp.async.wait_group 0;\n" ::);
        }
        __syncthreads();   // all warps see tile t; also: all reads of tile t-1 done
        if (t + 2 < nT) {
            int ns = stg + 2; if (ns >= 3) ns -= 3;
            cpTile(t + 2, ns);   // overwrites stage of tile t-1 (reads ordered above)
        }

        const unsigned* As = smem + stg * BUFF;
        const unsigned* Bs = As + AU;
#pragma unroll
        for (int ks = 0; ks < 2; ks++) {
            const int kb = ks * 8;          // u32 col base (A) / kp row base (B)
            unsigned a[2][4];
            unsigned b[NT][2];
#pragma unroll
            for (int mt = 0; mt < 2; mt++) {
                int m = wm * 32 + mt * 16 + gid;
                a[mt][0] = As[m * ASTR + kb + tig];
                a[mt][1] = As[(m + 8) * ASTR + kb + tig];
                a[mt][2] = As[m * ASTR + kb + tig + 4];
                a[mt][3] = As[(m + 8) * ASTR + kb + tig + 4];
            }
#pragma unroll
            for (int nt = 0; nt < NT; nt++) {
                int n = wn * (BN / 2) + nt * 8 + gid;
                b[nt][0] = Bs[(kb + tig) * BSTR + n];
                b[nt][1] = Bs[(kb + tig + 4) * BSTR + n];
            }
#pragma unroll
            for (int mt = 0; mt < 2; mt++)
#pragma unroll
                for (int nt = 0; nt < NT; nt++) {
                    asm volatile(
                        "mma.sync.aligned.m16n8k16.row.col.f32.bf16.bf16.f32 "
                        "{%0,%1,%2,%3}, {%4,%5,%6,%7}, {%8,%9}, {%0,%1,%2,%3};\n"
                        : "+f"(acc[mt][nt][0]), "+f"(acc[mt][nt][1]),
                          "+f"(acc[mt][nt][2]), "+f"(acc[mt][nt][3])
                        : "r"(a[mt][0]), "r"(a[mt][1]), "r"(a[mt][2]), "r"(a[mt][3]),
                          "r"(b[nt][0]), "r"(b[nt][1]));
                }
        }
        stg++; if (stg >= 3) stg = 0;
    }

    // ---------------- epilogue ----------------
#pragma unroll
    for (int mt = 0; mt < 2; mt++) {
        const int r0 = rowBase + wm * 32 + mt * 16 + gid;
        const int r1 = r0 + 8;
#pragma unroll
        for (int nt = 0; nt < NT; nt++) {
            const int cn = colBase + wn * (BN / 2) + nt * 8 + tig * 2;
            float bias0 = b1[cn], bias1 = b1[cn + 1];
            if (DUAL) { bias0 += b2[cn]; bias1 += b2[cn + 1]; }
            float v0 = acc[mt][nt][0] + bias0;
            float v1 = acc[mt][nt][1] + bias1;
            float v2 = acc[mt][nt][2] + bias0;
            float v3 = acc[mt][nt][3] + bias1;
            if (r0 < M) {
                if (ADDM) {
                    unsigned q = *(const unsigned*)(addM + (size_t)r0 * NC + cn);
                    float2 f = __bfloat1622float2(*(const bf162*)&q);
                    v0 += f.x; v1 += f.y;
                }
                if (ACT == 1) { v0 = gelu_f(v0); v1 = gelu_f(v1); }
                if (OUTBF) {
                    bf162 o = __float22bfloat162_rn(make_float2(v0, v1));
                    *(unsigned*)((bf16*)outv + (size_t)r0 * NC + cn) = *(unsigned*)&o;
                } else {
                    *(float2*)((float*)outv + (size_t)r0 * NC + cn) = make_float2(v0, v1);
                }
            }
            if (r1 < M) {
                if (ADDM) {
                    unsigned q = *(const unsigned*)(addM + (size_t)r1 * NC + cn);
                    float2 f = __bfloat1622float2(*(const bf162*)&q);
                    v2 += f.x; v3 += f.y;
                }
                if (ACT == 1) { v2 = gelu_f(v2); v3 = gelu_f(v3); }
                if (OUTBF) {
                    bf162 o = __float22bfloat162_rn(make_float2(v2, v3));
                    *(unsigned*)((bf16*)outv + (size_t)r1 * NC + cn) = *(unsigned*)&o;
                } else {
                    *(float2*)((float*)outv + (size_t)r1 * NC + cn) = make_float2(v2, v3);
                }
            }
        }
    }
}

// ------- LayerNorm(d=256) + GELU, warp per row (bf16 in/out, fp32 math) ----
__global__ void ln_gelu_kernel(const bf16* __restrict__ in, const float* __restrict__ g,
                               const float* __restrict__ be, bf16* __restrict__ out,
                               int M) {
    int row  = blockIdx.x * 8 + (threadIdx.x >> 5);
    int lane = threadIdx.x & 31;
    if (row >= M) return;
    uint4 q = *(const uint4*)(in + (size_t)row * 256 + lane * 8);
    const bf162* b2 = (const bf162*)&q;
    float v[8];
#pragma unroll
    for (int c = 0; c < 4; c++) {
        float2 f = __bfloat1622float2(b2[c]);
        v[2 * c] = f.x; v[2 * c + 1] = f.y;
    }
    float s = 0.f;
#pragma unroll
    for (int c = 0; c < 8; c++) s += v[c];
#pragma unroll
    for (int o = 16; o; o >>= 1) s += __shfl_xor_sync(0xffffffffu, s, o);
    float mean = s * (1.0f / 256.0f);
    float var = 0.f;
#pragma unroll
    for (int c = 0; c < 8; c++) { float d = v[c] - mean; var += d * d; }
#pragma unroll
    for (int o = 16; o; o >>= 1) var += __shfl_xor_sync(0xffffffffu, var, o);
    float rstd = rsqrtf(var * (1.0f / 256.0f) + 1e-5f);

    int c0 = lane * 8;
    float4 g0 = *(const float4*)(g + c0),  g1 = *(const float4*)(g + c0 + 4);
    float4 e0 = *(const float4*)(be + c0), e1 = *(const float4*)(be + c0 + 4);
    float gg[8] = {g0.x, g0.y, g0.z, g0.w, g1.x, g1.y, g1.z, g1.w};
    float ee[8] = {e0.x, e0.y, e0.z, e0.w, e1.x, e1.y, e1.z, e1.w};
    float o[8];
#pragma unroll
    for (int c = 0; c < 8; c++)
        o[c] = gelu_f((v[c] - mean) * rstd * gg[c] + ee[c]);
    uint4 w;
    bf162* wb = (bf162*)&w;
#pragma unroll
    for (int c = 0; c < 4; c++)
        wb[c] = __float22bfloat162_rn(make_float2(o[2 * c], o[2 * c + 1]));
    *(uint4*)(out + (size_t)row * 256 + lane * 8) = w;
}

// ---------------- log_softmax over 64 cols, warp per row, in-place ----------------
__global__ void lsm_kernel(float* __restrict__ io, int M) {
    int row  = blockIdx.x * 8 + (threadIdx.x >> 5);
    int lane = threadIdx.x & 31;
    if (row >= M) return;
    float* r = io + (size_t)row * 64;
    float2 v = *(float2*)(r + lane * 2);
    float m = fmaxf(v.x, v.y);
#pragma unroll
    for (int o = 16; o; o >>= 1) m = fmaxf(m, __shfl_xor_sync(0xffffffffu, m, o));
    float s = expf(v.x - m) + expf(v.y - m);
#pragma unroll
    for (int o = 16; o; o >>= 1) s += __shfl_xor_sync(0xffffffffu, s, o);
    float l = m + logf(s);
    v.x -= l; v.y -= l;
    *(float2*)(r + lane * 2) = v;
}

// ---------------- host orchestration ----------------
extern "C" void kernel_launch(void* const* d_in, const int* in_sizes, int n_in,
                              void* d_out, int out_size) {
    const float* x   = (const float*)d_in[0];
    const int*   ei  = (const int*)d_in[1];
    const int*   src = ei;
    const int*   dst = ei + EE;
    const float* Wc[3] = {(const float*)d_in[2],  (const float*)d_in[8],  (const float*)d_in[14]};
    const float* bc[3] = {(const float*)d_in[3],  (const float*)d_in[9],  (const float*)d_in[15]};
    const float* Wp[3] = {(const float*)d_in[4],  (const float*)d_in[10], (const float*)d_in[16]};
    const float* bp[3] = {(const float*)d_in[5],  (const float*)d_in[11], (const float*)d_in[17]};
    const float* gn[3] = {(const float*)d_in[6],  (const float*)d_in[12], (const float*)d_in[18]};
    const float* be[3] = {(const float*)d_in[7],  (const float*)d_in[13], (const float*)d_in[19]};
    const float* W_in = (const float*)d_in[20];
    const float* b_in = (const float*)d_in[21];
    const float* Wf1  = (const float*)d_in[22];
    const float* bf1  = (const float*)d_in[23];
    const float* Wf2  = (const float*)d_in[24];
    const float* bf2  = (const float*)d_in[25];
    float* outp = (float*)d_out;

    bf16 *p, *sA, *sB, *h, *u, *xb;
    unsigned* wpack;
    float *dv, *csrw;
    int *dg, *rowptr, *cur, *tmp, *bsum, *csrs;
    cudaGetSymbolAddress((void**)&p,  g_p);
    cudaGetSymbolAddress((void**)&sA, g_sA);
    cudaGetSymbolAddress((void**)&sB, g_sB);
    cudaGetSymbolAddress((void**)&h,  g_h);
    cudaGetSymbolAddress((void**)&u,  g_u);
    cudaGetSymbolAddress((void**)&xb, g_xb);
    cudaGetSymbolAddress((void**)&wpack, g_wpack);
    cudaGetSymbolAddress((void**)&dv, g_dinv);
    cudaGetSymbolAddress((void**)&dg, g_deg);
    cudaGetSymbolAddress((void**)&rowptr, g_rowptr);
    cudaGetSymbolAddress((void**)&cur, g_cur);
    cudaGetSymbolAddress((void**)&tmp, g_tmp);
    cudaGetSymbolAddress((void**)&bsum, g_bsum);
    cudaGetSymbolAddress((void**)&csrs, g_csrs);
    cudaGetSymbolAddress((void**)&csrw, g_csrw);

    // ---- pack weights (u32 [K/2][N]) + convert x -> bf16 ----
    unsigned* wc0p = wpack;           unsigned* wc1p = wpack + 16384;
    unsigned* wc2p = wpack + 49152;   unsigned* wp0p = wpack + 81920;
    unsigned* wp1p = wpack + 98304;   unsigned* wp2p = wpack + 131072;
    unsigned* winp = wpack + 163840;  unsigned* wf1p = wpack + 180224;
    unsigned* wf2p = wpack + 245760;
    PackArgs pa;
    pa.seg[0] = {Wc[0], wc0p, 256, 0, 16384};
    pa.seg[1] = {Wc[1], wc1p, 256, 0, 32768};
    pa.seg[2] = {Wc[2], wc2p, 256, 0, 32768};
    pa.seg[3] = {Wp[0], wp0p, 256, 0, 16384};
    pa.seg[4] = {Wp[1], wp1p, 256, 0, 32768};
    pa.seg[5] = {Wp[2], wp2p, 256, 0, 32768};
    pa.seg[6] = {W_in,  winp, 256, 0, 16384};
    pa.seg[7] = {Wf1,   wf1p, 512, 0, 65536};
    pa.seg[8] = {Wf2,   wf2p, 64,  0, 16384};
    pa.seg[9] = {x, (unsigned*)xb, 0, 1, (unsigned)(NN * 64)};
    pa.total = 16384 + 32768 + 32768 + 16384 + 32768 + 32768 + 16384 + 65536 + 16384
             + (unsigned)(NN * 64);
    pack_kernel<<<(pa.total + 255) / 256, 256>>>(pa);

    // ---- CSR build ----
    const int NB = (NN + 1023) / 1024;   // 49
    cudaMemsetAsync(dg, 0, NN * sizeof(int));
    deg_kernel<<<(EE + 255) / 256, 256>>>(dst, dg, EE);
    dinv_kernel<<<(NN + 255) / 256, 256>>>(dg, dv, NN);
    scan_blk<<<NB, 1024>>>(dg, tmp, bsum, NN);
    scan_top<<<1, 64>>>(bsum, NB);
    scan_add<<<(NN + 1 + 255) / 256, 256>>>(tmp, bsum, rowptr, cur, NN);
    fill_kernel<<<(EE + 255) / 256, 256>>>(src, dst, dv, cur, csrs, csrw, EE);

    // 3-stage smem sizes (> 48KB for BN=128 -> need attribute)
    const int SMEM128 = 3 * (128 * 20 + 16 * 136) * 4;   // 56832 B
    const int SMEM64  = 3 * (128 * 20 + 16 * 72)  * 4;   // 44544 B
    cudaFuncSetAttribute(bf16_gemm<128, 0, true,  false, true>,
                         cudaFuncAttributeMaxDynamicSharedMemorySize, SMEM128);
    cudaFuncSetAttribute(bf16_gemm<128, 0, false, true,  true>,
                         cudaFuncAttributeMaxDynamicSharedMemorySize, SMEM128);
    cudaFuncSetAttribute(bf16_gemm<128, 1, false, false, true>,
                         cudaFuncAttributeMaxDynamicSharedMemorySize, SMEM128);
    cudaFuncSetAttribute(bf16_gemm<64,  0, false, false, false>,
                         cudaFuncAttributeMaxDynamicSharedMemorySize, SMEM64);

    const dim3 gridN256(2, (NN + 127) / 128);
    const dim3 gridN512(4, (NN + 127) / 128);
    const dim3 gridN64 (1, (NN + 127) / 128);
    const int gGather = (NN + 7) / 8;    // 6250 blocks, warp per row

    const unsigned* WcP[3] = {wc0p, wc1p, wc2p};
    const unsigned* WpP[3] = {wp0p, wp1p, wp2p};

    const bf16* hin  = xb;   int din   = 128;
    const bf16* skip = xb;   int dskip = 128;
    bf16* snew_arr[3] = {sA, sB, sA};

    for (int l = 0; l < 3; l++) {
        if (din == 128)
            gather_warp<128><<<gGather, 256>>>(hin, dv, rowptr, csrs, csrw, p);
        else
            gather_warp<256><<<gGather, 256>>>(hin, dv, rowptr, csrs, csrw, p);
        bf16* snew = snew_arr[l];
        bf16_gemm<128, 0, true, false, true><<<gridN256, 256, SMEM128>>>(
            p, WcP[l], din, skip, WpP[l], dskip,
            bc[l], bp[l], nullptr, snew, NN, 256);
        ln_gelu_kernel<<<(NN + 7) / 8, 256>>>(snew, gn[l], be[l], h, NN);
        hin = h; din = 256;
        skip = snew; dskip = 256;
    }

    // t = x @ W_in + b_in + h   (sB free after layer 2 consumed it as skip)
    bf16_gemm<128, 0, false, true, true><<<gridN256, 256, SMEM128>>>(
        xb, winp, 128, nullptr, nullptr, 0, b_in, nullptr, h, sB, NN, 256);
    // u = gelu(t @ Wf1 + bf1)
    bf16_gemm<128, 1, false, false, true><<<gridN512, 256, SMEM128>>>(
        sB, wf1p, 256, nullptr, nullptr, 0, bf1, nullptr, nullptr, u, NN, 512);
    // logits = u @ Wf2 + bf2  -> d_out (fp32)
    bf16_gemm<64, 0, false, false, false><<<gridN64, 256, SMEM64>>>(
        u, wf2p, 512, nullptr, nullptr, 0, bf2, nullptr, nullptr, outp, NN, 64);
    // in-place log_softmax
    lsm_kernel<<<(NN + 7) / 8, 256>>>(outp, NN);
}